// round 9
// baseline (speedup 1.0000x reference)
#include <cuda_runtime.h>
#include <math.h>

#define BB 4
#define SS 2048
#define DD 1024
#define HH 16
#define DK 64
#define M_TOT (BB * SS)

// Scratch buffers (allocation-free rule: __device__ globals)
__device__ float g_q[M_TOT * DD];
__device__ float g_k[M_TOT * DD];
__device__ float g_v[M_TOT * DD];
__device__ float g_ctx[M_TOT * DD];

// ---------------------------------------------------------------------------
// GEMM: C[m][n] = sum_k A[m][k] * W[n][k]
// Tile 128x128x16, 256 threads, 8x8 microtile.  (Proven function-equivalent
// to the naive GEMM: R2/R5 vs R6 rel_err identical to 7 digits.)
// ---------------------------------------------------------------------------
__global__ __launch_bounds__(256) void gemm_nt(const float* __restrict__ A,
                                               const float* __restrict__ W,
                                               float* __restrict__ C) {
    __shared__ __align__(16) float As[16][128];
    __shared__ __align__(16) float Bs[16][128];

    const int tid  = threadIdx.x;
    const int m0   = blockIdx.y * 128;
    const int n0   = blockIdx.x * 128;
    const int row0 = (tid >> 4) * 8;
    const int col0 = (tid & 15) * 8;

    float acc[8][8];
#pragma unroll
    for (int i = 0; i < 8; i++)
#pragma unroll
        for (int j = 0; j < 8; j++) acc[i][j] = 0.0f;

    for (int k0 = 0; k0 < 1024; k0 += 16) {
        __syncthreads();
#pragma unroll
        for (int l = 0; l < 2; l++) {
            int idx = tid + l * 256;
            int r   = idx >> 2;
            int c   = (idx & 3) * 4;
            float4 av = *(const float4*)(A + (size_t)(m0 + r) * 1024 + k0 + c);
            As[c + 0][r] = av.x;
            As[c + 1][r] = av.y;
            As[c + 2][r] = av.z;
            As[c + 3][r] = av.w;
            float4 bv = *(const float4*)(W + (size_t)(n0 + r) * 1024 + k0 + c);
            Bs[c + 0][r] = bv.x;
            Bs[c + 1][r] = bv.y;
            Bs[c + 2][r] = bv.z;
            Bs[c + 3][r] = bv.w;
        }
        __syncthreads();
#pragma unroll
        for (int kk = 0; kk < 16; kk++) {
            float a[8], b[8];
            *(float4*)&a[0] = *(const float4*)&As[kk][row0];
            *(float4*)&a[4] = *(const float4*)&As[kk][row0 + 4];
            *(float4*)&b[0] = *(const float4*)&Bs[kk][col0];
            *(float4*)&b[4] = *(const float4*)&Bs[kk][col0 + 4];
#pragma unroll
            for (int i = 0; i < 8; i++)
#pragma unroll
                for (int j = 0; j < 8; j++)
                    acc[i][j] = fmaf(a[i], b[j], acc[i][j]);
        }
    }

#pragma unroll
    for (int i = 0; i < 8; i++)
#pragma unroll
        for (int j = 0; j < 8; j += 4) {
            float4 v = make_float4(acc[i][j], acc[i][j + 1], acc[i][j + 2], acc[i][j + 3]);
            *(float4*)(C + (size_t)(m0 + row0 + i) * 1024 + n0 + col0 + j) = v;
        }
}

// ---------------------------------------------------------------------------
// RoPE, interleaved pairing, SIGN-FLIPPED rotation (by -theta) —
// THE SINGLE VARIABLE UNDER TEST THIS ROUND:
//   out[2j]   = x[2j] cos + x[2j+1] sin
//   out[2j+1] = -x[2j] sin + x[2j+1] cos
// ---------------------------------------------------------------------------
__global__ __launch_bounds__(256) void rope_kernel() {
    int idx = blockIdx.x * 256 + threadIdx.x;
    int j = idx & 31;
    int h = (idx >> 5) & 15;
    int s = (idx >> 9) & 2047;
    int b = idx >> 20;

    float inv_freq = powf(10000.0f, -((float)(2 * j)) / 64.0f);
    float angle = (float)s * inv_freq;
    float c, sn;
    sincosf(angle, &c, &sn);

    size_t base = ((size_t)(b * SS + s)) * DD + h * DK + 2 * j;

    float q1 = g_q[base], q2 = g_q[base + 1];
    g_q[base]     = q1 * c + q2 * sn;      // sign-flipped
    g_q[base + 1] = -q1 * sn + q2 * c;     // sign-flipped

    float k1 = g_k[base], k2 = g_k[base + 1];
    g_k[base]     = k1 * c + k2 * sn;      // sign-flipped
    g_k[base + 1] = -k1 * sn + k2 * c;     // sign-flipped
}

// ---------------------------------------------------------------------------
// Flash attention (fp32, causal), R5 version (proven function-equivalent to
// the naive attention: identical rel_err to 7 digits).
// ---------------------------------------------------------------------------
#define TPAD 68
#define PPAD 65

__global__ __launch_bounds__(256) void attn_kernel() {
    extern __shared__ __align__(16) float sm[];
    float* Qs = sm;
    float* Ks = Qs + 64 * TPAD;
    float* Vs = Ks + 64 * TPAD;
    float* Ps = Vs + 64 * TPAD;
    float* Mrow = Ps + 64 * PPAD;
    float* Lrow = Mrow + 64;
    float* Arow = Lrow + 64;

    const int tid = threadIdx.x;
    const int ty = tid >> 4, tx = tid & 15;
    const int qt = blockIdx.x, h = blockIdx.y, b = blockIdx.z;
    const int q0 = qt * 64;
    const float scale = 0.125f;
    const size_t base_bh = (size_t)b * SS * DD + h * DK;

    for (int i = tid; i < 64 * 16; i += 256) {
        int r  = i >> 4;
        int d4 = (i & 15) << 2;
        float4 val = *(const float4*)(g_q + base_bh + (size_t)(q0 + r) * DD + d4);
        Qs[(d4 + 0) * TPAD + r] = val.x;
        Qs[(d4 + 1) * TPAD + r] = val.y;
        Qs[(d4 + 2) * TPAD + r] = val.z;
        Qs[(d4 + 3) * TPAD + r] = val.w;
    }
    if (tid < 64) {
        Mrow[tid] = -INFINITY;
        Lrow[tid] = 0.0f;
    }

    float o[4][4];
#pragma unroll
    for (int i = 0; i < 4; i++)
#pragma unroll
        for (int j = 0; j < 4; j++) o[i][j] = 0.0f;

    for (int kt = 0; kt <= qt; kt++) {
        const int k0 = kt * 64;
        __syncthreads();
        for (int i = tid; i < 64 * 16; i += 256) {
            int c  = i >> 4;
            int d4 = (i & 15) << 2;
            float4 kv = *(const float4*)(g_k + base_bh + (size_t)(k0 + c) * DD + d4);
            Ks[(d4 + 0) * TPAD + c] = kv.x;
            Ks[(d4 + 1) * TPAD + c] = kv.y;
            Ks[(d4 + 2) * TPAD + c] = kv.z;
            Ks[(d4 + 3) * TPAD + c] = kv.w;
            float4 vv = *(const float4*)(g_v + base_bh + (size_t)(k0 + c) * DD + d4);
            *(float4*)&Vs[c * TPAD + d4] = vv;
        }
        __syncthreads();

        float s[4][4];
#pragma unroll
        for (int i = 0; i < 4; i++)
#pragma unroll
            for (int j = 0; j < 4; j++) s[i][j] = 0.0f;

#pragma unroll 8
        for (int d = 0; d < 64; d++) {
            float4 qv = *(const float4*)&Qs[d * TPAD + 4 * ty];
            float4 kv = *(const float4*)&Ks[d * TPAD + 4 * tx];
            float qa[4] = {qv.x, qv.y, qv.z, qv.w};
            float ka[4] = {kv.x, kv.y, kv.z, kv.w};
#pragma unroll
            for (int i = 0; i < 4; i++)
#pragma unroll
                for (int j = 0; j < 4; j++)
                    s[i][j] = fmaf(qa[i], ka[j], s[i][j]);
        }

#pragma unroll
        for (int i = 0; i < 4; i++)
#pragma unroll
            for (int j = 0; j < 4; j++) {
                float val = s[i][j] * scale;
                if (kt == qt && (k0 + 4 * tx + j) > (q0 + 4 * ty + i))
                    val = -INFINITY;
                Ps[(4 * ty + i) * PPAD + 4 * tx + j] = val;
            }
        __syncthreads();

        if (tid < 64) {
            float* row = Ps + tid * PPAD;
            float rmax = row[0];
#pragma unroll 8
            for (int c = 1; c < 64; c++) rmax = fmaxf(rmax, row[c]);
            float m_old = Mrow[tid];
            float mn = fmaxf(m_old, rmax);
            float alpha = (m_old == -INFINITY) ? 0.0f : expf(m_old - mn);
            float psum = 0.0f;
#pragma unroll 8
            for (int c = 0; c < 64; c++) {
                float sv = row[c];
                float p = (sv == -INFINITY) ? 0.0f : expf(sv - mn);
                row[c] = p;
                psum += p;
            }
            Lrow[tid] = Lrow[tid] * alpha + psum;
            Mrow[tid] = mn;
            Arow[tid] = alpha;
        }
        __syncthreads();

        float al[4];
#pragma unroll
        for (int i = 0; i < 4; i++) {
            al[i] = Arow[4 * ty + i];
#pragma unroll
            for (int j = 0; j < 4; j++) o[i][j] *= al[i];
        }

#pragma unroll 8
        for (int c = 0; c < 64; c++) {
            float4 vv = *(const float4*)&Vs[c * TPAD + 4 * tx];
            float va[4] = {vv.x, vv.y, vv.z, vv.w};
#pragma unroll
            for (int i = 0; i < 4; i++) {
                float pv = Ps[(4 * ty + i) * PPAD + c];
#pragma unroll
                for (int j = 0; j < 4; j++)
                    o[i][j] = fmaf(pv, va[j], o[i][j]);
            }
        }
    }

    __syncthreads();

#pragma unroll
    for (int i = 0; i < 4; i++) {
        float inv = 1.0f / Lrow[4 * ty + i];
        float4 res = make_float4(o[i][0] * inv, o[i][1] * inv,
                                 o[i][2] * inv, o[i][3] * inv);
        *(float4*)(g_ctx + base_bh + (size_t)(q0 + 4 * ty + i) * DD + 4 * tx) = res;
    }
}

// ---------------------------------------------------------------------------
extern "C" void kernel_launch(void* const* d_in, const int* in_sizes, int n_in,
                              void* d_out, int out_size) {
    const float* x  = (const float*)d_in[0];
    const float* wq = (const float*)d_in[1];
    const float* wk = (const float*)d_in[2];
    const float* wv = (const float*)d_in[3];
    const float* wo = (const float*)d_in[4];
    float* out = (float*)d_out;

    float *q, *k, *v, *ctx;
    cudaGetSymbolAddress((void**)&q,   g_q);
    cudaGetSymbolAddress((void**)&k,   g_k);
    cudaGetSymbolAddress((void**)&v,   g_v);
    cudaGetSymbolAddress((void**)&ctx, g_ctx);

    const int attn_smem = (3 * 64 * TPAD + 64 * PPAD + 3 * 64) * sizeof(float);
    cudaFuncSetAttribute(attn_kernel, cudaFuncAttributeMaxDynamicSharedMemorySize,
                         attn_smem);

    dim3 ggrid(1024 / 128, M_TOT / 128);  // (8, 64)
    gemm_nt<<<ggrid, 256>>>(x, wq, q);
    gemm_nt<<<ggrid, 256>>>(x, wk, k);
    gemm_nt<<<ggrid, 256>>>(x, wv, v);

    rope_kernel<<<(BB * SS * HH * (DK / 2)) / 256, 256>>>();

    attn_kernel<<<dim3(SS / 64, HH, BB), 256, attn_smem>>>();

    gemm_nt<<<ggrid, 256>>>(ctx, wo, out);
}

// round 10
// speedup vs baseline: 1.4775x; 1.4775x over previous
#include <cuda_runtime.h>
#include <math.h>
#include <stdint.h>

#define BB 4
#define SS 2048
#define DD 1024
#define HH 16
#define DK 64
#define M_TOT (BB * SS)

// Scratch buffers (allocation-free rule: __device__ globals)
__device__ float g_q[M_TOT * DD];
__device__ float g_k[M_TOT * DD];
__device__ float g_v[M_TOT * DD];
__device__ float g_ctx[M_TOT * DD];

// ---------------------------------------------------------------------------
// tf32 -> uint32 bits (round to nearest)
// ---------------------------------------------------------------------------
__device__ __forceinline__ uint32_t f2tf32(float x) {
    uint32_t r;
    asm("cvt.rna.tf32.f32 %0, %1;" : "=r"(r) : "f"(x));
    return r;
}

// ---------------------------------------------------------------------------
// TF32 tensor-core GEMM: C[m][n] = sum_k A[m][k] * W[n][k]
// Block tile 128x128, k-tile 32. 8 warps (4 m x 2 n), warp tile 32x64.
// mma.sync.aligned.m16n8k8.row.col.f32.tf32.tf32.f32
// Smem row-major [128][36]: pad 36 gives conflict-free fragment loads
// (bank = (4g+tg)%32) and conflict-free float4 staging stores.
// ---------------------------------------------------------------------------
#define KP 36

__global__ __launch_bounds__(256) void gemm_tf32(const float* __restrict__ A,
                                                 const float* __restrict__ W,
                                                 float* __restrict__ C) {
    __shared__ uint32_t As[128 * KP];   // [m][k] tf32 bits
    __shared__ uint32_t Bs[128 * KP];   // [n][k] tf32 bits

    const int tid  = threadIdx.x;
    const int warp = tid >> 5;
    const int lane = tid & 31;
    const int wm = (warp & 3) * 32;     // warp m offset in tile
    const int wn = (warp >> 2) * 64;    // warp n offset in tile
    const int g  = lane >> 2;           // group id 0..7
    const int tg = lane & 3;            // thread-in-group 0..3
    const int m0 = blockIdx.y * 128;
    const int n0 = blockIdx.x * 128;

    float acc[2][8][4];
#pragma unroll
    for (int mt = 0; mt < 2; mt++)
#pragma unroll
        for (int nt = 0; nt < 8; nt++)
#pragma unroll
            for (int i = 0; i < 4; i++) acc[mt][nt][i] = 0.0f;

    for (int k0 = 0; k0 < DD; k0 += 32) {
        __syncthreads();
        // Stage A and W tiles (128 rows x 32 k), converting to tf32.
#pragma unroll
        for (int l = 0; l < 4; l++) {
            int idx = l * 256 + tid;
            int r   = idx >> 3;          // 0..127
            int c   = (idx & 7) << 2;    // 0,4,...,28
            float4 av = *(const float4*)(A + (size_t)(m0 + r) * DD + k0 + c);
            uint32_t* pa = &As[r * KP + c];
            pa[0] = f2tf32(av.x); pa[1] = f2tf32(av.y);
            pa[2] = f2tf32(av.z); pa[3] = f2tf32(av.w);
            float4 bv = *(const float4*)(W + (size_t)(n0 + r) * DD + k0 + c);
            uint32_t* pb = &Bs[r * KP + c];
            pb[0] = f2tf32(bv.x); pb[1] = f2tf32(bv.y);
            pb[2] = f2tf32(bv.z); pb[3] = f2tf32(bv.w);
        }
        __syncthreads();

#pragma unroll
        for (int ks = 0; ks < 32; ks += 8) {
            // A fragments for both 16-row m-tiles
            uint32_t a[2][4];
#pragma unroll
            for (int mt = 0; mt < 2; mt++) {
                int mr = wm + mt * 16;
                a[mt][0] = As[(mr + g) * KP + ks + tg];
                a[mt][1] = As[(mr + g + 8) * KP + ks + tg];
                a[mt][2] = As[(mr + g) * KP + ks + tg + 4];
                a[mt][3] = As[(mr + g + 8) * KP + ks + tg + 4];
            }
#pragma unroll
            for (int nt = 0; nt < 8; nt++) {
                int nc = wn + nt * 8;
                uint32_t b0 = Bs[(nc + g) * KP + ks + tg];
                uint32_t b1 = Bs[(nc + g) * KP + ks + tg + 4];
#pragma unroll
                for (int mt = 0; mt < 2; mt++) {
                    asm volatile(
                        "mma.sync.aligned.m16n8k8.row.col.f32.tf32.tf32.f32 "
                        "{%0,%1,%2,%3}, {%4,%5,%6,%7}, {%8,%9}, {%0,%1,%2,%3};\n"
                        : "+f"(acc[mt][nt][0]), "+f"(acc[mt][nt][1]),
                          "+f"(acc[mt][nt][2]), "+f"(acc[mt][nt][3])
                        : "r"(a[mt][0]), "r"(a[mt][1]), "r"(a[mt][2]), "r"(a[mt][3]),
                          "r"(b0), "r"(b1));
                }
            }
        }
    }

    // Writeback: c0,c1 -> (row+g, 2tg), c2,c3 -> (row+g+8, 2tg)
#pragma unroll
    for (int mt = 0; mt < 2; mt++) {
        int row = m0 + wm + mt * 16;
#pragma unroll
        for (int nt = 0; nt < 8; nt++) {
            int col = n0 + wn + nt * 8 + 2 * tg;
            *(float2*)(C + (size_t)(row + g) * DD + col) =
                make_float2(acc[mt][nt][0], acc[mt][nt][1]);
            *(float2*)(C + (size_t)(row + g + 8) * DD + col) =
                make_float2(acc[mt][nt][2], acc[mt][nt][3]);
        }
    }
}

// ---------------------------------------------------------------------------
// RoPE, interleaved pairing, rotation by -theta (verified in Round 9):
//   out[2j]   = x[2j] cos + x[2j+1] sin
//   out[2j+1] = -x[2j] sin + x[2j+1] cos
// ---------------------------------------------------------------------------
__global__ __launch_bounds__(256) void rope_kernel() {
    int idx = blockIdx.x * 256 + threadIdx.x;
    int j = idx & 31;
    int h = (idx >> 5) & 15;
    int s = (idx >> 9) & 2047;
    int b = idx >> 20;

    float inv_freq = powf(10000.0f, -((float)(2 * j)) / 64.0f);
    float angle = (float)s * inv_freq;
    float c, sn;
    sincosf(angle, &c, &sn);

    size_t base = ((size_t)(b * SS + s)) * DD + h * DK + 2 * j;

    float q1 = g_q[base], q2 = g_q[base + 1];
    g_q[base]     = q1 * c + q2 * sn;
    g_q[base + 1] = -q1 * sn + q2 * c;

    float k1 = g_k[base], k2 = g_k[base + 1];
    g_k[base]     = k1 * c + k2 * sn;
    g_k[base + 1] = -k1 * sn + k2 * c;
}

// ---------------------------------------------------------------------------
// Flash attention (fp32, causal) — unchanged from the passing Round 9 kernel.
// ---------------------------------------------------------------------------
#define TPAD 68
#define PPAD 65

__global__ __launch_bounds__(256) void attn_kernel() {
    extern __shared__ __align__(16) float sm[];
    float* Qs = sm;
    float* Ks = Qs + 64 * TPAD;
    float* Vs = Ks + 64 * TPAD;
    float* Ps = Vs + 64 * TPAD;
    float* Mrow = Ps + 64 * PPAD;
    float* Lrow = Mrow + 64;
    float* Arow = Lrow + 64;

    const int tid = threadIdx.x;
    const int ty = tid >> 4, tx = tid & 15;
    const int qt = blockIdx.x, h = blockIdx.y, b = blockIdx.z;
    const int q0 = qt * 64;
    const float scale = 0.125f;
    const size_t base_bh = (size_t)b * SS * DD + h * DK;

    for (int i = tid; i < 64 * 16; i += 256) {
        int r  = i >> 4;
        int d4 = (i & 15) << 2;
        float4 val = *(const float4*)(g_q + base_bh + (size_t)(q0 + r) * DD + d4);
        Qs[(d4 + 0) * TPAD + r] = val.x;
        Qs[(d4 + 1) * TPAD + r] = val.y;
        Qs[(d4 + 2) * TPAD + r] = val.z;
        Qs[(d4 + 3) * TPAD + r] = val.w;
    }
    if (tid < 64) {
        Mrow[tid] = -INFINITY;
        Lrow[tid] = 0.0f;
    }

    float o[4][4];
#pragma unroll
    for (int i = 0; i < 4; i++)
#pragma unroll
        for (int j = 0; j < 4; j++) o[i][j] = 0.0f;

    for (int kt = 0; kt <= qt; kt++) {
        const int k0 = kt * 64;
        __syncthreads();
        for (int i = tid; i < 64 * 16; i += 256) {
            int c  = i >> 4;
            int d4 = (i & 15) << 2;
            float4 kv = *(const float4*)(g_k + base_bh + (size_t)(k0 + c) * DD + d4);
            Ks[(d4 + 0) * TPAD + c] = kv.x;
            Ks[(d4 + 1) * TPAD + c] = kv.y;
            Ks[(d4 + 2) * TPAD + c] = kv.z;
            Ks[(d4 + 3) * TPAD + c] = kv.w;
            float4 vv = *(const float4*)(g_v + base_bh + (size_t)(k0 + c) * DD + d4);
            *(float4*)&Vs[c * TPAD + d4] = vv;
        }
        __syncthreads();

        float s[4][4];
#pragma unroll
        for (int i = 0; i < 4; i++)
#pragma unroll
            for (int j = 0; j < 4; j++) s[i][j] = 0.0f;

#pragma unroll 8
        for (int d = 0; d < 64; d++) {
            float4 qv = *(const float4*)&Qs[d * TPAD + 4 * ty];
            float4 kv = *(const float4*)&Ks[d * TPAD + 4 * tx];
            float qa[4] = {qv.x, qv.y, qv.z, qv.w};
            float ka[4] = {kv.x, kv.y, kv.z, kv.w};
#pragma unroll
            for (int i = 0; i < 4; i++)
#pragma unroll
                for (int j = 0; j < 4; j++)
                    s[i][j] = fmaf(qa[i], ka[j], s[i][j]);
        }

#pragma unroll
        for (int i = 0; i < 4; i++)
#pragma unroll
            for (int j = 0; j < 4; j++) {
                float val = s[i][j] * scale;
                if (kt == qt && (k0 + 4 * tx + j) > (q0 + 4 * ty + i))
                    val = -INFINITY;
                Ps[(4 * ty + i) * PPAD + 4 * tx + j] = val;
            }
        __syncthreads();

        if (tid < 64) {
            float* row = Ps + tid * PPAD;
            float rmax = row[0];
#pragma unroll 8
            for (int c = 1; c < 64; c++) rmax = fmaxf(rmax, row[c]);
            float m_old = Mrow[tid];
            float mn = fmaxf(m_old, rmax);
            float alpha = (m_old == -INFINITY) ? 0.0f : expf(m_old - mn);
            float psum = 0.0f;
#pragma unroll 8
            for (int c = 0; c < 64; c++) {
                float sv = row[c];
                float p = (sv == -INFINITY) ? 0.0f : expf(sv - mn);
                row[c] = p;
                psum += p;
            }
            Lrow[tid] = Lrow[tid] * alpha + psum;
            Mrow[tid] = mn;
            Arow[tid] = alpha;
        }
        __syncthreads();

        float al[4];
#pragma unroll
        for (int i = 0; i < 4; i++) {
            al[i] = Arow[4 * ty + i];
#pragma unroll
            for (int j = 0; j < 4; j++) o[i][j] *= al[i];
        }

#pragma unroll 8
        for (int c = 0; c < 64; c++) {
            float4 vv = *(const float4*)&Vs[c * TPAD + 4 * tx];
            float va[4] = {vv.x, vv.y, vv.z, vv.w};
#pragma unroll
            for (int i = 0; i < 4; i++) {
                float pv = Ps[(4 * ty + i) * PPAD + c];
#pragma unroll
                for (int j = 0; j < 4; j++)
                    o[i][j] = fmaf(pv, va[j], o[i][j]);
            }
        }
    }

    __syncthreads();

#pragma unroll
    for (int i = 0; i < 4; i++) {
        float inv = 1.0f / Lrow[4 * ty + i];
        float4 res = make_float4(o[i][0] * inv, o[i][1] * inv,
                                 o[i][2] * inv, o[i][3] * inv);
        *(float4*)(g_ctx + base_bh + (size_t)(q0 + 4 * ty + i) * DD + 4 * tx) = res;
    }
}

// ---------------------------------------------------------------------------
extern "C" void kernel_launch(void* const* d_in, const int* in_sizes, int n_in,
                              void* d_out, int out_size) {
    const float* x  = (const float*)d_in[0];
    const float* wq = (const float*)d_in[1];
    const float* wk = (const float*)d_in[2];
    const float* wv = (const float*)d_in[3];
    const float* wo = (const float*)d_in[4];
    float* out = (float*)d_out;

    float *q, *k, *v, *ctx;
    cudaGetSymbolAddress((void**)&q,   g_q);
    cudaGetSymbolAddress((void**)&k,   g_k);
    cudaGetSymbolAddress((void**)&v,   g_v);
    cudaGetSymbolAddress((void**)&ctx, g_ctx);

    const int attn_smem = (3 * 64 * TPAD + 64 * PPAD + 3 * 64) * sizeof(float);
    cudaFuncSetAttribute(attn_kernel, cudaFuncAttributeMaxDynamicSharedMemorySize,
                         attn_smem);

    dim3 ggrid(DD / 128, M_TOT / 128);  // (8, 64)
    gemm_tf32<<<ggrid, 256>>>(x, wq, q);
    gemm_tf32<<<ggrid, 256>>>(x, wk, k);
    gemm_tf32<<<ggrid, 256>>>(x, wv, v);

    rope_kernel<<<(BB * SS * HH * (DK / 2)) / 256, 256>>>();

    attn_kernel<<<dim3(SS / 64, HH, BB), 256, attn_smem>>>();

    gemm_tf32<<<ggrid, 256>>>(ctx, wo, out);
}

// round 11
// speedup vs baseline: 2.2705x; 1.5367x over previous
#include <cuda_runtime.h>
#include <math.h>
#include <stdint.h>

#define BB 4
#define SS 2048
#define DD 1024
#define HH 16
#define DK 64
#define M_TOT (BB * SS)

// Scratch buffers (allocation-free rule: __device__ globals)
__device__ float g_q[M_TOT * DD];
__device__ float g_k[M_TOT * DD];
__device__ float g_v[M_TOT * DD];
__device__ float g_ctx[M_TOT * DD];

__device__ __forceinline__ uint32_t f2tf32(float x) {
    uint32_t r;
    asm("cvt.rna.tf32.f32 %0, %1;" : "=r"(r) : "f"(x));
    return r;
}

__device__ __forceinline__ void mma_tf32(float* c, const uint32_t* a,
                                         uint32_t b0, uint32_t b1) {
    asm volatile(
        "mma.sync.aligned.m16n8k8.row.col.f32.tf32.tf32.f32 "
        "{%0,%1,%2,%3}, {%4,%5,%6,%7}, {%8,%9}, {%0,%1,%2,%3};\n"
        : "+f"(c[0]), "+f"(c[1]), "+f"(c[2]), "+f"(c[3])
        : "r"(a[0]), "r"(a[1]), "r"(a[2]), "r"(a[3]), "r"(b0), "r"(b1));
}

// ---------------------------------------------------------------------------
// TF32 tensor-core GEMM (unchanged from Round 10 — validated).
// ---------------------------------------------------------------------------
#define KP 36

__global__ __launch_bounds__(256) void gemm_tf32(const float* __restrict__ A,
                                                 const float* __restrict__ W,
                                                 float* __restrict__ C) {
    __shared__ uint32_t As[128 * KP];
    __shared__ uint32_t Bs[128 * KP];

    const int tid  = threadIdx.x;
    const int warp = tid >> 5;
    const int lane = tid & 31;
    const int wm = (warp & 3) * 32;
    const int wn = (warp >> 2) * 64;
    const int g  = lane >> 2;
    const int tg = lane & 3;
    const int m0 = blockIdx.y * 128;
    const int n0 = blockIdx.x * 128;

    float acc[2][8][4];
#pragma unroll
    for (int mt = 0; mt < 2; mt++)
#pragma unroll
        for (int nt = 0; nt < 8; nt++)
#pragma unroll
            for (int i = 0; i < 4; i++) acc[mt][nt][i] = 0.0f;

    for (int k0 = 0; k0 < DD; k0 += 32) {
        __syncthreads();
#pragma unroll
        for (int l = 0; l < 4; l++) {
            int idx = l * 256 + tid;
            int r   = idx >> 3;
            int c   = (idx & 7) << 2;
            float4 av = *(const float4*)(A + (size_t)(m0 + r) * DD + k0 + c);
            uint32_t* pa = &As[r * KP + c];
            pa[0] = f2tf32(av.x); pa[1] = f2tf32(av.y);
            pa[2] = f2tf32(av.z); pa[3] = f2tf32(av.w);
            float4 bv = *(const float4*)(W + (size_t)(n0 + r) * DD + k0 + c);
            uint32_t* pb = &Bs[r * KP + c];
            pb[0] = f2tf32(bv.x); pb[1] = f2tf32(bv.y);
            pb[2] = f2tf32(bv.z); pb[3] = f2tf32(bv.w);
        }
        __syncthreads();

#pragma unroll
        for (int ks = 0; ks < 32; ks += 8) {
            uint32_t a[2][4];
#pragma unroll
            for (int mt = 0; mt < 2; mt++) {
                int mr = wm + mt * 16;
                a[mt][0] = As[(mr + g) * KP + ks + tg];
                a[mt][1] = As[(mr + g + 8) * KP + ks + tg];
                a[mt][2] = As[(mr + g) * KP + ks + tg + 4];
                a[mt][3] = As[(mr + g + 8) * KP + ks + tg + 4];
            }
#pragma unroll
            for (int nt = 0; nt < 8; nt++) {
                int nc = wn + nt * 8;
                uint32_t b0 = Bs[(nc + g) * KP + ks + tg];
                uint32_t b1 = Bs[(nc + g) * KP + ks + tg + 4];
#pragma unroll
                for (int mt = 0; mt < 2; mt++)
                    mma_tf32(acc[mt][nt], a[mt], b0, b1);
            }
        }
    }

#pragma unroll
    for (int mt = 0; mt < 2; mt++) {
        int row = m0 + wm + mt * 16;
#pragma unroll
        for (int nt = 0; nt < 8; nt++) {
            int col = n0 + wn + nt * 8 + 2 * tg;
            *(float2*)(C + (size_t)(row + g) * DD + col) =
                make_float2(acc[mt][nt][0], acc[mt][nt][1]);
            *(float2*)(C + (size_t)(row + g + 8) * DD + col) =
                make_float2(acc[mt][nt][2], acc[mt][nt][3]);
        }
    }
}

// ---------------------------------------------------------------------------
// RoPE, interleaved, rotation by -theta (verified Round 9).
// ---------------------------------------------------------------------------
__global__ __launch_bounds__(256) void rope_kernel() {
    int idx = blockIdx.x * 256 + threadIdx.x;
    int j = idx & 31;
    int h = (idx >> 5) & 15;
    int s = (idx >> 9) & 2047;
    int b = idx >> 20;

    float inv_freq = powf(10000.0f, -((float)(2 * j)) / 64.0f);
    float angle = (float)s * inv_freq;
    float c, sn;
    sincosf(angle, &c, &sn);

    size_t base = ((size_t)(b * SS + s)) * DD + h * DK + 2 * j;

    float q1 = g_q[base], q2 = g_q[base + 1];
    g_q[base]     = q1 * c + q2 * sn;
    g_q[base + 1] = -q1 * sn + q2 * c;

    float k1 = g_k[base], k2 = g_k[base + 1];
    g_k[base]     = k1 * c + k2 * sn;
    g_k[base + 1] = -k1 * sn + k2 * c;
}

// ---------------------------------------------------------------------------
// Tensor-core flash attention (tf32 MMA, causal, online softmax).
// Block = 128 q-rows of one (b,h); 8 warps x 16 rows; 64-wide K tiles.
// Fragment layouts identical to gemm_tf32 (validated in Round 10).
// ---------------------------------------------------------------------------
#define AP 68   // smem stride (words) for Ps/Ks/Vt

__global__ __launch_bounds__(256) void attn_tc() {
    extern __shared__ __align__(16) uint32_t smu[];
    uint32_t* Ps = smu;               // [128][AP]  Q staging, then P tiles
    uint32_t* Ks = Ps + 128 * AP;     // [64][AP]   K tile, natural [c][d]
    uint32_t* Vt = Ks + 64 * AP;      // [64][AP]   V tile transposed [d][c]

    const int tid  = threadIdx.x;
    const int w    = tid >> 5;
    const int lane = tid & 31;
    const int g    = lane >> 2;
    const int tg   = lane & 3;
    const int w16  = w * 16;

    const int qt = blockIdx.x, h = blockIdx.y, b = blockIdx.z;
    const int q0 = qt * 128;
    const size_t base_bh = (size_t)b * SS * DD + h * DK;
    const float scale = 0.125f;

    // ---- Stage Q (128 x 64) as tf32 into Ps, then lift to registers ----
    for (int i = tid; i < 128 * 16; i += 256) {
        int r  = i >> 4;
        int c4 = (i & 15) << 2;
        float4 val = *(const float4*)(g_q + base_bh + (size_t)(q0 + r) * DD + c4);
        uint32_t* p = &Ps[r * AP + c4];
        p[0] = f2tf32(val.x); p[1] = f2tf32(val.y);
        p[2] = f2tf32(val.z); p[3] = f2tf32(val.w);
    }
    __syncthreads();

    uint32_t aq[8][4];
#pragma unroll
    for (int ks = 0; ks < 8; ks++) {
        aq[ks][0] = Ps[(w16 + g) * AP + ks * 8 + tg];
        aq[ks][1] = Ps[(w16 + g + 8) * AP + ks * 8 + tg];
        aq[ks][2] = Ps[(w16 + g) * AP + ks * 8 + tg + 4];
        aq[ks][3] = Ps[(w16 + g + 8) * AP + ks * 8 + tg + 4];
    }

    // Online softmax state: thread owns rows (w16+g) and (w16+g+8)
    float m0 = -INFINITY, m1 = -INFINITY, l0 = 0.0f, l1 = 0.0f;
    float o[8][4];
#pragma unroll
    for (int nt = 0; nt < 8; nt++)
#pragma unroll
        for (int i = 0; i < 4; i++) o[nt][i] = 0.0f;

    const int row_lo = q0 + w16;          // min row of this warp
    const int row_hi = row_lo + 15;       // max row of this warp
    const int ktmax  = 2 * qt + 1;        // tiles covering rows [q0, q0+127]

    for (int kt = 0; kt <= ktmax; kt++) {
        const int k0 = kt * 64;
        __syncthreads();
        // Stage K tile natural [c][d], V tile transposed [d][c]
        for (int i = tid; i < 64 * 16; i += 256) {
            int c  = i >> 4;
            int d4 = (i & 15) << 2;
            float4 kv = *(const float4*)(g_k + base_bh + (size_t)(k0 + c) * DD + d4);
            uint32_t* pk = &Ks[c * AP + d4];
            pk[0] = f2tf32(kv.x); pk[1] = f2tf32(kv.y);
            pk[2] = f2tf32(kv.z); pk[3] = f2tf32(kv.w);
            float4 vv = *(const float4*)(g_v + base_bh + (size_t)(k0 + c) * DD + d4);
            Vt[(d4 + 0) * AP + c] = f2tf32(vv.x);
            Vt[(d4 + 1) * AP + c] = f2tf32(vv.y);
            Vt[(d4 + 2) * AP + c] = f2tf32(vv.z);
            Vt[(d4 + 3) * AP + c] = f2tf32(vv.w);
        }
        __syncthreads();

        if (k0 > row_hi) continue;   // tile entirely above this warp's rows

        // ---- S = Q K^T : rows 16 x cols 64 per warp ----
        float s[8][4];
#pragma unroll
        for (int nt = 0; nt < 8; nt++)
#pragma unroll
            for (int i = 0; i < 4; i++) s[nt][i] = 0.0f;

#pragma unroll
        for (int ks = 0; ks < 8; ks++) {
#pragma unroll
            for (int nt = 0; nt < 8; nt++) {
                uint32_t b0 = Ks[(nt * 8 + g) * AP + ks * 8 + tg];
                uint32_t b1 = Ks[(nt * 8 + g) * AP + ks * 8 + tg + 4];
                mma_tf32(s[nt], aq[ks], b0, b1);
            }
        }

        // ---- scale + causal mask ----
        const bool full = (k0 + 63 <= row_lo);
#pragma unroll
        for (int nt = 0; nt < 8; nt++) {
#pragma unroll
            for (int i = 0; i < 4; i++) {
                float val = s[nt][i] * scale;
                if (!full) {
                    int col = k0 + nt * 8 + 2 * tg + (i & 1);
                    int row = row_lo + g + ((i & 2) ? 8 : 0);
                    if (col > row) val = -INFINITY;
                }
                s[nt][i] = val;
            }
        }

        // ---- online softmax update (rows g and g+8) ----
        float r0 = -INFINITY, r1 = -INFINITY;
#pragma unroll
        for (int nt = 0; nt < 8; nt++) {
            r0 = fmaxf(r0, fmaxf(s[nt][0], s[nt][1]));
            r1 = fmaxf(r1, fmaxf(s[nt][2], s[nt][3]));
        }
        r0 = fmaxf(r0, __shfl_xor_sync(0xffffffffu, r0, 1));
        r0 = fmaxf(r0, __shfl_xor_sync(0xffffffffu, r0, 2));
        r1 = fmaxf(r1, __shfl_xor_sync(0xffffffffu, r1, 1));
        r1 = fmaxf(r1, __shfl_xor_sync(0xffffffffu, r1, 2));

        float mn0 = fmaxf(m0, r0), mn1 = fmaxf(m1, r1);
        float al0 = (m0 == -INFINITY) ? 0.0f : __expf(m0 - mn0);
        float al1 = (m1 == -INFINITY) ? 0.0f : __expf(m1 - mn1);

        float ps0 = 0.0f, ps1 = 0.0f;
#pragma unroll
        for (int nt = 0; nt < 8; nt++) {
            float p0 = __expf(s[nt][0] - mn0);
            float p1 = __expf(s[nt][1] - mn0);
            float p2 = __expf(s[nt][2] - mn1);
            float p3 = __expf(s[nt][3] - mn1);
            s[nt][0] = p0; s[nt][1] = p1; s[nt][2] = p2; s[nt][3] = p3;
            ps0 += p0 + p1;
            ps1 += p2 + p3;
        }
        ps0 += __shfl_xor_sync(0xffffffffu, ps0, 1);
        ps0 += __shfl_xor_sync(0xffffffffu, ps0, 2);
        ps1 += __shfl_xor_sync(0xffffffffu, ps1, 1);
        ps1 += __shfl_xor_sync(0xffffffffu, ps1, 2);

        l0 = l0 * al0 + ps0;
        l1 = l1 * al1 + ps1;
        m0 = mn0;
        m1 = mn1;

#pragma unroll
        for (int nt = 0; nt < 8; nt++) {
            o[nt][0] *= al0; o[nt][1] *= al0;
            o[nt][2] *= al1; o[nt][3] *= al1;
        }

        // ---- stage P (tf32) into this warp's rows of Ps ----
#pragma unroll
        for (int nt = 0; nt < 8; nt++) {
            Ps[(w16 + g) * AP + nt * 8 + 2 * tg]         = f2tf32(s[nt][0]);
            Ps[(w16 + g) * AP + nt * 8 + 2 * tg + 1]     = f2tf32(s[nt][1]);
            Ps[(w16 + g + 8) * AP + nt * 8 + 2 * tg]     = f2tf32(s[nt][2]);
            Ps[(w16 + g + 8) * AP + nt * 8 + 2 * tg + 1] = f2tf32(s[nt][3]);
        }
        __syncwarp();

        // ---- O += P V : rows 16 x d 64 per warp ----
#pragma unroll
        for (int ks = 0; ks < 8; ks++) {
            uint32_t ap[4];
            ap[0] = Ps[(w16 + g) * AP + ks * 8 + tg];
            ap[1] = Ps[(w16 + g + 8) * AP + ks * 8 + tg];
            ap[2] = Ps[(w16 + g) * AP + ks * 8 + tg + 4];
            ap[3] = Ps[(w16 + g + 8) * AP + ks * 8 + tg + 4];
#pragma unroll
            for (int nt = 0; nt < 8; nt++) {
                uint32_t b0 = Vt[(nt * 8 + g) * AP + ks * 8 + tg];
                uint32_t b1 = Vt[(nt * 8 + g) * AP + ks * 8 + tg + 4];
                mma_tf32(o[nt], ap, b0, b1);
            }
        }
        __syncwarp();   // Ps reads done before next iteration's stores
    }

    // ---- normalize + write ctx ----
    const float inv0 = 1.0f / l0;
    const float inv1 = 1.0f / l1;
#pragma unroll
    for (int nt = 0; nt < 8; nt++) {
        int col = nt * 8 + 2 * tg;
        *(float2*)(g_ctx + base_bh + (size_t)(q0 + w16 + g) * DD + col) =
            make_float2(o[nt][0] * inv0, o[nt][1] * inv0);
        *(float2*)(g_ctx + base_bh + (size_t)(q0 + w16 + g + 8) * DD + col) =
            make_float2(o[nt][2] * inv1, o[nt][3] * inv1);
    }
}

// ---------------------------------------------------------------------------
extern "C" void kernel_launch(void* const* d_in, const int* in_sizes, int n_in,
                              void* d_out, int out_size) {
    const float* x  = (const float*)d_in[0];
    const float* wq = (const float*)d_in[1];
    const float* wk = (const float*)d_in[2];
    const float* wv = (const float*)d_in[3];
    const float* wo = (const float*)d_in[4];
    float* out = (float*)d_out;

    float *q, *k, *v, *ctx;
    cudaGetSymbolAddress((void**)&q,   g_q);
    cudaGetSymbolAddress((void**)&k,   g_k);
    cudaGetSymbolAddress((void**)&v,   g_v);
    cudaGetSymbolAddress((void**)&ctx, g_ctx);

    const int attn_smem = (128 * AP + 64 * AP + 64 * AP) * 4;  // 69632 bytes
    cudaFuncSetAttribute(attn_tc, cudaFuncAttributeMaxDynamicSharedMemorySize,
                         attn_smem);

    dim3 ggrid(DD / 128, M_TOT / 128);  // (8, 64)
    gemm_tf32<<<ggrid, 256>>>(x, wq, q);
    gemm_tf32<<<ggrid, 256>>>(x, wk, k);
    gemm_tf32<<<ggrid, 256>>>(x, wv, v);

    rope_kernel<<<(BB * SS * HH * (DK / 2)) / 256, 256>>>();

    attn_tc<<<dim3(SS / 128, HH, BB), 256, attn_smem>>>();

    gemm_tf32<<<ggrid, 256>>>(ctx, wo, out);
}

// round 12
// speedup vs baseline: 2.6209x; 1.1543x over previous
#include <cuda_runtime.h>
#include <math.h>
#include <stdint.h>

#define BB 4
#define SS 2048
#define DD 1024
#define HH 16
#define DK 64
#define M_TOT (BB * SS)

// Scratch buffers (allocation-free rule: __device__ globals)
__device__ float g_q[M_TOT * DD];
__device__ float g_k[M_TOT * DD];
__device__ float g_v[M_TOT * DD];
__device__ float g_ctx[M_TOT * DD];

__device__ __forceinline__ uint32_t f2tf32(float x) {
    uint32_t r;
    asm("cvt.rna.tf32.f32 %0, %1;" : "=r"(r) : "f"(x));
    return r;
}

__device__ __forceinline__ void mma_tf32(float* c, const uint32_t* a,
                                         uint32_t b0, uint32_t b1) {
    asm volatile(
        "mma.sync.aligned.m16n8k8.row.col.f32.tf32.tf32.f32 "
        "{%0,%1,%2,%3}, {%4,%5,%6,%7}, {%8,%9}, {%0,%1,%2,%3};\n"
        : "+f"(c[0]), "+f"(c[1]), "+f"(c[2]), "+f"(c[3])
        : "r"(a[0]), "r"(a[1]), "r"(a[2]), "r"(a[3]), "r"(b0), "r"(b1));
}

// ---------------------------------------------------------------------------
// TF32 GEMM core: C[m][n] = sum_k A[m][k] * W[n][k]
// Block tile 128x128, k-tile 32, 8 warps (4m x 2n), warp tile 32x64.
// Software-pipelined: register prefetch of next k-tile + double-buffered
// smem; ONE __syncthreads per k-iteration.
// ---------------------------------------------------------------------------
#define KP 36
#define BUFW (128 * KP)

__device__ __forceinline__ void gemm_core(const float* __restrict__ A,
                                          const float* __restrict__ W,
                                          float* __restrict__ C,
                                          int m0, int n0, uint32_t* dsm) {
    uint32_t* As = dsm;              // [2][128][KP]
    uint32_t* Bs = dsm + 2 * BUFW;   // [2][128][KP]

    const int tid  = threadIdx.x;
    const int warp = tid >> 5;
    const int lane = tid & 31;
    const int wm = (warp & 3) * 32;
    const int wn = (warp >> 2) * 64;
    const int g  = lane >> 2;
    const int tg = lane & 3;

    int rr[4], cc[4];
#pragma unroll
    for (int l = 0; l < 4; l++) {
        int idx = l * 256 + tid;
        rr[l] = idx >> 3;           // 0..127
        cc[l] = (idx & 7) << 2;     // 0,4,...,28
    }

    float acc[2][8][4];
#pragma unroll
    for (int mt = 0; mt < 2; mt++)
#pragma unroll
        for (int nt = 0; nt < 8; nt++)
#pragma unroll
            for (int i = 0; i < 4; i++) acc[mt][nt][i] = 0.0f;

    // Prologue: load k-tile 0 and stage into buffer 0
    float4 ra[4], rb[4];
#pragma unroll
    for (int l = 0; l < 4; l++) {
        ra[l] = *(const float4*)(A + (size_t)(m0 + rr[l]) * DD + cc[l]);
        rb[l] = *(const float4*)(W + (size_t)(n0 + rr[l]) * DD + cc[l]);
    }
#pragma unroll
    for (int l = 0; l < 4; l++) {
        uint32_t* pa = &As[rr[l] * KP + cc[l]];
        pa[0] = f2tf32(ra[l].x); pa[1] = f2tf32(ra[l].y);
        pa[2] = f2tf32(ra[l].z); pa[3] = f2tf32(ra[l].w);
        uint32_t* pb = &Bs[rr[l] * KP + cc[l]];
        pb[0] = f2tf32(rb[l].x); pb[1] = f2tf32(rb[l].y);
        pb[2] = f2tf32(rb[l].z); pb[3] = f2tf32(rb[l].w);
    }
    __syncthreads();

    for (int kt = 0; kt < 32; kt++) {
        const uint32_t* Ac = As + (kt & 1) * BUFW;
        const uint32_t* Bc = Bs + (kt & 1) * BUFW;

        // Prefetch next k-tile into registers (overlaps with MMAs below)
        if (kt < 31) {
            const int k0 = (kt + 1) * 32;
#pragma unroll
            for (int l = 0; l < 4; l++) {
                ra[l] = *(const float4*)(A + (size_t)(m0 + rr[l]) * DD + k0 + cc[l]);
                rb[l] = *(const float4*)(W + (size_t)(n0 + rr[l]) * DD + k0 + cc[l]);
            }
        }

        // MMAs over current stage
#pragma unroll
        for (int ks = 0; ks < 32; ks += 8) {
            uint32_t a[2][4];
#pragma unroll
            for (int mt = 0; mt < 2; mt++) {
                int mr = wm + mt * 16;
                a[mt][0] = Ac[(mr + g) * KP + ks + tg];
                a[mt][1] = Ac[(mr + g + 8) * KP + ks + tg];
                a[mt][2] = Ac[(mr + g) * KP + ks + tg + 4];
                a[mt][3] = Ac[(mr + g + 8) * KP + ks + tg + 4];
            }
#pragma unroll
            for (int nt = 0; nt < 8; nt++) {
                int nc = wn + nt * 8;
                uint32_t b0 = Bc[(nc + g) * KP + ks + tg];
                uint32_t b1 = Bc[(nc + g) * KP + ks + tg + 4];
#pragma unroll
                for (int mt = 0; mt < 2; mt++)
                    mma_tf32(acc[mt][nt], a[mt], b0, b1);
            }
        }

        // Stage prefetched tile into the other buffer
        if (kt < 31) {
            uint32_t* An = As + ((kt + 1) & 1) * BUFW;
            uint32_t* Bn = Bs + ((kt + 1) & 1) * BUFW;
#pragma unroll
            for (int l = 0; l < 4; l++) {
                uint32_t* pa = &An[rr[l] * KP + cc[l]];
                pa[0] = f2tf32(ra[l].x); pa[1] = f2tf32(ra[l].y);
                pa[2] = f2tf32(ra[l].z); pa[3] = f2tf32(ra[l].w);
                uint32_t* pb = &Bn[rr[l] * KP + cc[l]];
                pb[0] = f2tf32(rb[l].x); pb[1] = f2tf32(rb[l].y);
                pb[2] = f2tf32(rb[l].z); pb[3] = f2tf32(rb[l].w);
            }
            __syncthreads();
        }
    }

#pragma unroll
    for (int mt = 0; mt < 2; mt++) {
        int row = m0 + wm + mt * 16;
#pragma unroll
        for (int nt = 0; nt < 8; nt++) {
            int col = n0 + wn + nt * 8 + 2 * tg;
            *(float2*)(C + (size_t)(row + g) * DD + col) =
                make_float2(acc[mt][nt][0], acc[mt][nt][1]);
            *(float2*)(C + (size_t)(row + g + 8) * DD + col) =
                make_float2(acc[mt][nt][2], acc[mt][nt][3]);
        }
    }
}

#define GEMM_SMEM (4 * BUFW * 4)   // 73728 bytes

// Fused Q/K/V projections: blockIdx.x in [0,24): /8 selects matrix+dest.
__global__ __launch_bounds__(256) void gemm_qkv(const float* __restrict__ x,
                                                const float* __restrict__ wq,
                                                const float* __restrict__ wk,
                                                const float* __restrict__ wv) {
    extern __shared__ __align__(16) uint32_t dsm[];
    const int which = blockIdx.x >> 3;
    const int n0 = (blockIdx.x & 7) * 128;
    const float* W = (which == 0) ? wq : (which == 1) ? wk : wv;
    float* C = (which == 0) ? g_q : (which == 1) ? g_k : g_v;
    gemm_core(x, W, C, blockIdx.y * 128, n0, dsm);
}

// O projection
__global__ __launch_bounds__(256) void gemm_o(const float* __restrict__ W,
                                              float* __restrict__ out) {
    extern __shared__ __align__(16) uint32_t dsm[];
    gemm_core(g_ctx, W, out, blockIdx.y * 128, blockIdx.x * 128, dsm);
}

// ---------------------------------------------------------------------------
// RoPE, interleaved, rotation by -theta (verified Round 9).
// ---------------------------------------------------------------------------
__global__ __launch_bounds__(256) void rope_kernel() {
    int idx = blockIdx.x * 256 + threadIdx.x;
    int j = idx & 31;
    int h = (idx >> 5) & 15;
    int s = (idx >> 9) & 2047;
    int b = idx >> 20;

    float inv_freq = powf(10000.0f, -((float)(2 * j)) / 64.0f);
    float angle = (float)s * inv_freq;
    float c, sn;
    sincosf(angle, &c, &sn);

    size_t base = ((size_t)(b * SS + s)) * DD + h * DK + 2 * j;

    float q1 = g_q[base], q2 = g_q[base + 1];
    g_q[base]     = q1 * c + q2 * sn;
    g_q[base + 1] = -q1 * sn + q2 * c;

    float k1 = g_k[base], k2 = g_k[base + 1];
    g_k[base]     = k1 * c + k2 * sn;
    g_k[base + 1] = -k1 * sn + k2 * c;
}

// ---------------------------------------------------------------------------
// Tensor-core flash attention (tf32 MMA) — unchanged from passing Round 11.
// ---------------------------------------------------------------------------
#define AP 68

__global__ __launch_bounds__(256) void attn_tc() {
    extern __shared__ __align__(16) uint32_t smu[];
    uint32_t* Ps = smu;
    uint32_t* Ks = Ps + 128 * AP;
    uint32_t* Vt = Ks + 64 * AP;

    const int tid  = threadIdx.x;
    const int w    = tid >> 5;
    const int lane = tid & 31;
    const int g    = lane >> 2;
    const int tg   = lane & 3;
    const int w16  = w * 16;

    const int qt = blockIdx.x, h = blockIdx.y, b = blockIdx.z;
    const int q0 = qt * 128;
    const size_t base_bh = (size_t)b * SS * DD + h * DK;
    const float scale = 0.125f;

    for (int i = tid; i < 128 * 16; i += 256) {
        int r  = i >> 4;
        int c4 = (i & 15) << 2;
        float4 val = *(const float4*)(g_q + base_bh + (size_t)(q0 + r) * DD + c4);
        uint32_t* p = &Ps[r * AP + c4];
        p[0] = f2tf32(val.x); p[1] = f2tf32(val.y);
        p[2] = f2tf32(val.z); p[3] = f2tf32(val.w);
    }
    __syncthreads();

    uint32_t aq[8][4];
#pragma unroll
    for (int ks = 0; ks < 8; ks++) {
        aq[ks][0] = Ps[(w16 + g) * AP + ks * 8 + tg];
        aq[ks][1] = Ps[(w16 + g + 8) * AP + ks * 8 + tg];
        aq[ks][2] = Ps[(w16 + g) * AP + ks * 8 + tg + 4];
        aq[ks][3] = Ps[(w16 + g + 8) * AP + ks * 8 + tg + 4];
    }

    float m0 = -INFINITY, m1 = -INFINITY, l0 = 0.0f, l1 = 0.0f;
    float o[8][4];
#pragma unroll
    for (int nt = 0; nt < 8; nt++)
#pragma unroll
        for (int i = 0; i < 4; i++) o[nt][i] = 0.0f;

    const int row_lo = q0 + w16;
    const int row_hi = row_lo + 15;
    const int ktmax  = 2 * qt + 1;

    for (int kt = 0; kt <= ktmax; kt++) {
        const int k0 = kt * 64;
        __syncthreads();
        for (int i = tid; i < 64 * 16; i += 256) {
            int c  = i >> 4;
            int d4 = (i & 15) << 2;
            float4 kv = *(const float4*)(g_k + base_bh + (size_t)(k0 + c) * DD + d4);
            uint32_t* pk = &Ks[c * AP + d4];
            pk[0] = f2tf32(kv.x); pk[1] = f2tf32(kv.y);
            pk[2] = f2tf32(kv.z); pk[3] = f2tf32(kv.w);
            float4 vv = *(const float4*)(g_v + base_bh + (size_t)(k0 + c) * DD + d4);
            Vt[(d4 + 0) * AP + c] = f2tf32(vv.x);
            Vt[(d4 + 1) * AP + c] = f2tf32(vv.y);
            Vt[(d4 + 2) * AP + c] = f2tf32(vv.z);
            Vt[(d4 + 3) * AP + c] = f2tf32(vv.w);
        }
        __syncthreads();

        if (k0 > row_hi) continue;

        float s[8][4];
#pragma unroll
        for (int nt = 0; nt < 8; nt++)
#pragma unroll
            for (int i = 0; i < 4; i++) s[nt][i] = 0.0f;

#pragma unroll
        for (int ks = 0; ks < 8; ks++) {
#pragma unroll
            for (int nt = 0; nt < 8; nt++) {
                uint32_t b0 = Ks[(nt * 8 + g) * AP + ks * 8 + tg];
                uint32_t b1 = Ks[(nt * 8 + g) * AP + ks * 8 + tg + 4];
                mma_tf32(s[nt], aq[ks], b0, b1);
            }
        }

        const bool full = (k0 + 63 <= row_lo);
#pragma unroll
        for (int nt = 0; nt < 8; nt++) {
#pragma unroll
            for (int i = 0; i < 4; i++) {
                float val = s[nt][i] * scale;
                if (!full) {
                    int col = k0 + nt * 8 + 2 * tg + (i & 1);
                    int row = row_lo + g + ((i & 2) ? 8 : 0);
                    if (col > row) val = -INFINITY;
                }
                s[nt][i] = val;
            }
        }

        float r0 = -INFINITY, r1 = -INFINITY;
#pragma unroll
        for (int nt = 0; nt < 8; nt++) {
            r0 = fmaxf(r0, fmaxf(s[nt][0], s[nt][1]));
            r1 = fmaxf(r1, fmaxf(s[nt][2], s[nt][3]));
        }
        r0 = fmaxf(r0, __shfl_xor_sync(0xffffffffu, r0, 1));
        r0 = fmaxf(r0, __shfl_xor_sync(0xffffffffu, r0, 2));
        r1 = fmaxf(r1, __shfl_xor_sync(0xffffffffu, r1, 1));
        r1 = fmaxf(r1, __shfl_xor_sync(0xffffffffu, r1, 2));

        float mn0 = fmaxf(m0, r0), mn1 = fmaxf(m1, r1);
        float al0 = (m0 == -INFINITY) ? 0.0f : __expf(m0 - mn0);
        float al1 = (m1 == -INFINITY) ? 0.0f : __expf(m1 - mn1);

        float ps0 = 0.0f, ps1 = 0.0f;
#pragma unroll
        for (int nt = 0; nt < 8; nt++) {
            float p0 = __expf(s[nt][0] - mn0);
            float p1 = __expf(s[nt][1] - mn0);
            float p2 = __expf(s[nt][2] - mn1);
            float p3 = __expf(s[nt][3] - mn1);
            s[nt][0] = p0; s[nt][1] = p1; s[nt][2] = p2; s[nt][3] = p3;
            ps0 += p0 + p1;
            ps1 += p2 + p3;
        }
        ps0 += __shfl_xor_sync(0xffffffffu, ps0, 1);
        ps0 += __shfl_xor_sync(0xffffffffu, ps0, 2);
        ps1 += __shfl_xor_sync(0xffffffffu, ps1, 1);
        ps1 += __shfl_xor_sync(0xffffffffu, ps1, 2);

        l0 = l0 * al0 + ps0;
        l1 = l1 * al1 + ps1;
        m0 = mn0;
        m1 = mn1;

#pragma unroll
        for (int nt = 0; nt < 8; nt++) {
            o[nt][0] *= al0; o[nt][1] *= al0;
            o[nt][2] *= al1; o[nt][3] *= al1;
        }

#pragma unroll
        for (int nt = 0; nt < 8; nt++) {
            Ps[(w16 + g) * AP + nt * 8 + 2 * tg]         = f2tf32(s[nt][0]);
            Ps[(w16 + g) * AP + nt * 8 + 2 * tg + 1]     = f2tf32(s[nt][1]);
            Ps[(w16 + g + 8) * AP + nt * 8 + 2 * tg]     = f2tf32(s[nt][2]);
            Ps[(w16 + g + 8) * AP + nt * 8 + 2 * tg + 1] = f2tf32(s[nt][3]);
        }
        __syncwarp();

#pragma unroll
        for (int ks = 0; ks < 8; ks++) {
            uint32_t ap[4];
            ap[0] = Ps[(w16 + g) * AP + ks * 8 + tg];
            ap[1] = Ps[(w16 + g + 8) * AP + ks * 8 + tg];
            ap[2] = Ps[(w16 + g) * AP + ks * 8 + tg + 4];
            ap[3] = Ps[(w16 + g + 8) * AP + ks * 8 + tg + 4];
#pragma unroll
            for (int nt = 0; nt < 8; nt++) {
                uint32_t b0 = Vt[(nt * 8 + g) * AP + ks * 8 + tg];
                uint32_t b1 = Vt[(nt * 8 + g) * AP + ks * 8 + tg + 4];
                mma_tf32(o[nt], ap, b0, b1);
            }
        }
        __syncwarp();
    }

    const float inv0 = 1.0f / l0;
    const float inv1 = 1.0f / l1;
#pragma unroll
    for (int nt = 0; nt < 8; nt++) {
        int col = nt * 8 + 2 * tg;
        *(float2*)(g_ctx + base_bh + (size_t)(q0 + w16 + g) * DD + col) =
            make_float2(o[nt][0] * inv0, o[nt][1] * inv0);
        *(float2*)(g_ctx + base_bh + (size_t)(q0 + w16 + g + 8) * DD + col) =
            make_float2(o[nt][2] * inv1, o[nt][3] * inv1);
    }
}

// ---------------------------------------------------------------------------
extern "C" void kernel_launch(void* const* d_in, const int* in_sizes, int n_in,
                              void* d_out, int out_size) {
    const float* x  = (const float*)d_in[0];
    const float* wq = (const float*)d_in[1];
    const float* wk = (const float*)d_in[2];
    const float* wv = (const float*)d_in[3];
    const float* wo = (const float*)d_in[4];
    float* out = (float*)d_out;

    const int attn_smem = (128 * AP + 64 * AP + 64 * AP) * 4;  // 69632 bytes
    cudaFuncSetAttribute(attn_tc, cudaFuncAttributeMaxDynamicSharedMemorySize,
                         attn_smem);
    cudaFuncSetAttribute(gemm_qkv, cudaFuncAttributeMaxDynamicSharedMemorySize,
                         GEMM_SMEM);
    cudaFuncSetAttribute(gemm_o, cudaFuncAttributeMaxDynamicSharedMemorySize,
                         GEMM_SMEM);

    // Fused Q/K/V projections: 24 n-tiles x 64 m-tiles
    gemm_qkv<<<dim3(24, M_TOT / 128), 256, GEMM_SMEM>>>(x, wq, wk, wv);

    rope_kernel<<<(BB * SS * HH * (DK / 2)) / 256, 256>>>();

    attn_tc<<<dim3(SS / 128, HH, BB), 256, attn_smem>>>();

    gemm_o<<<dim3(DD / 128, M_TOT / 128), 256, GEMM_SMEM>>>(wo, out);
}

// round 13
// speedup vs baseline: 2.8075x; 1.0712x over previous
#include <cuda_runtime.h>
#include <math.h>
#include <stdint.h>

#define BB 4
#define SS 2048
#define DD 1024
#define HH 16
#define DK 64
#define M_TOT (BB * SS)

// Scratch buffers (allocation-free rule: __device__ globals)
__device__ float g_q[M_TOT * DD];
__device__ float g_k[M_TOT * DD];
__device__ float g_v[M_TOT * DD];
__device__ float g_ctx[M_TOT * DD];
// tf32-exact copies of GEMM operands
__device__ float g_x[M_TOT * DD];
__device__ float g_wq[DD * DD];
__device__ float g_wk[DD * DD];
__device__ float g_wv[DD * DD];
__device__ float g_wo[DD * DD];

__device__ __forceinline__ uint32_t f2tf32(float x) {
    uint32_t r;
    asm("cvt.rna.tf32.f32 %0, %1;" : "=r"(r) : "f"(x));
    return r;
}

__device__ __forceinline__ void mma_tf32(float* c, const uint32_t* a,
                                         uint32_t b0, uint32_t b1) {
    asm volatile(
        "mma.sync.aligned.m16n8k8.row.col.f32.tf32.tf32.f32 "
        "{%0,%1,%2,%3}, {%4,%5,%6,%7}, {%8,%9}, {%0,%1,%2,%3};\n"
        : "+f"(c[0]), "+f"(c[1]), "+f"(c[2]), "+f"(c[3])
        : "r"(a[0]), "r"(a[1]), "r"(a[2]), "r"(a[3]), "r"(b0), "r"(b1));
}

__device__ __forceinline__ void cpa16(void* smem_ptr, const void* gptr) {
    uint32_t sa = (uint32_t)__cvta_generic_to_shared(smem_ptr);
    asm volatile("cp.async.cg.shared.global [%0], [%1], 16;\n"
                 :: "r"(sa), "l"(gptr));
}
#define CP_COMMIT() asm volatile("cp.async.commit_group;\n" ::: "memory")
#define CP_WAIT0()  asm volatile("cp.async.wait_group 0;\n" ::: "memory")

// ---------------------------------------------------------------------------
// tf32 pre-rounding pass: out[i] = RNA_tf32(in[i])  (fp32-bit tf32-exact)
// ---------------------------------------------------------------------------
__global__ __launch_bounds__(256) void tf32_round(const float* __restrict__ in,
                                                  float* __restrict__ out) {
    int i = (blockIdx.x * 256 + threadIdx.x) * 4;
    float4 v = *(const float4*)(in + i);
    uint4 r;
    r.x = f2tf32(v.x); r.y = f2tf32(v.y);
    r.z = f2tf32(v.z); r.w = f2tf32(v.w);
    *(uint4*)(out + i) = r;
}

// ---------------------------------------------------------------------------
// TF32 GEMM core: C[m][n] = sum_k A[m][k] * W[n][k]
// A, W must be tf32-exact (pre-rounded). cp.async 2-stage pipeline,
// one wait_group + one __syncthreads per 32-k tile.
// Block tile 128x128, 8 warps (4m x 2n), warp tile 32x64.
// ---------------------------------------------------------------------------
#define KP 36
#define BUFW (128 * KP)
#define GEMM_SMEM (4 * BUFW * 4)   // 2 stages x (A+B) = 73728 bytes

__device__ __forceinline__ void gemm_core(const float* __restrict__ A,
                                          const float* __restrict__ W,
                                          float* __restrict__ C,
                                          int m0, int n0, uint32_t* dsm) {
    uint32_t* As = dsm;              // [2][128][KP]
    uint32_t* Bs = dsm + 2 * BUFW;   // [2][128][KP]

    const int tid  = threadIdx.x;
    const int warp = tid >> 5;
    const int lane = tid & 31;
    const int wm = (warp & 3) * 32;
    const int wn = (warp >> 2) * 64;
    const int g  = lane >> 2;
    const int tg = lane & 3;

    int rr[4], cc[4];
#pragma unroll
    for (int l = 0; l < 4; l++) {
        int idx = l * 256 + tid;
        rr[l] = idx >> 3;           // 0..127
        cc[l] = (idx & 7) << 2;     // 0,4,...,28 (words)
    }

    float acc[2][8][4];
#pragma unroll
    for (int mt = 0; mt < 2; mt++)
#pragma unroll
        for (int nt = 0; nt < 8; nt++)
#pragma unroll
            for (int i = 0; i < 4; i++) acc[mt][nt][i] = 0.0f;

    // Prologue: async-load k-tile 0 into buffer 0
#pragma unroll
    for (int l = 0; l < 4; l++) {
        cpa16(&As[rr[l] * KP + cc[l]], A + (size_t)(m0 + rr[l]) * DD + cc[l]);
        cpa16(&Bs[rr[l] * KP + cc[l]], W + (size_t)(n0 + rr[l]) * DD + cc[l]);
    }
    CP_COMMIT();

    for (int kt = 0; kt < 32; kt++) {
        CP_WAIT0();          // stage kt complete (only group outstanding)
        __syncthreads();     // visible everywhere; prior-iter reads done

        // Issue next stage (overlaps with MMAs below)
        if (kt < 31) {
            const int k0 = (kt + 1) * 32;
            uint32_t* An = As + ((kt + 1) & 1) * BUFW;
            uint32_t* Bn = Bs + ((kt + 1) & 1) * BUFW;
#pragma unroll
            for (int l = 0; l < 4; l++) {
                cpa16(&An[rr[l] * KP + cc[l]],
                      A + (size_t)(m0 + rr[l]) * DD + k0 + cc[l]);
                cpa16(&Bn[rr[l] * KP + cc[l]],
                      W + (size_t)(n0 + rr[l]) * DD + k0 + cc[l]);
            }
            CP_COMMIT();
        }

        const uint32_t* Ac = As + (kt & 1) * BUFW;
        const uint32_t* Bc = Bs + (kt & 1) * BUFW;

#pragma unroll
        for (int ks = 0; ks < 32; ks += 8) {
            uint32_t a[2][4];
#pragma unroll
            for (int mt = 0; mt < 2; mt++) {
                int mr = wm + mt * 16;
                a[mt][0] = Ac[(mr + g) * KP + ks + tg];
                a[mt][1] = Ac[(mr + g + 8) * KP + ks + tg];
                a[mt][2] = Ac[(mr + g) * KP + ks + tg + 4];
                a[mt][3] = Ac[(mr + g + 8) * KP + ks + tg + 4];
            }
#pragma unroll
            for (int nt = 0; nt < 8; nt++) {
                int nc = wn + nt * 8;
                uint32_t b0 = Bc[(nc + g) * KP + ks + tg];
                uint32_t b1 = Bc[(nc + g) * KP + ks + tg + 4];
#pragma unroll
                for (int mt = 0; mt < 2; mt++)
                    mma_tf32(acc[mt][nt], a[mt], b0, b1);
            }
        }
    }

#pragma unroll
    for (int mt = 0; mt < 2; mt++) {
        int row = m0 + wm + mt * 16;
#pragma unroll
        for (int nt = 0; nt < 8; nt++) {
            int col = n0 + wn + nt * 8 + 2 * tg;
            *(float2*)(C + (size_t)(row + g) * DD + col) =
                make_float2(acc[mt][nt][0], acc[mt][nt][1]);
            *(float2*)(C + (size_t)(row + g + 8) * DD + col) =
                make_float2(acc[mt][nt][2], acc[mt][nt][3]);
        }
    }
}

// Fused Q/K/V projections over pre-rounded x / weights.
__global__ __launch_bounds__(256, 2) void gemm_qkv() {
    extern __shared__ __align__(16) uint32_t dsm[];
    const int which = blockIdx.x >> 3;
    const int n0 = (blockIdx.x & 7) * 128;
    const float* W = (which == 0) ? g_wq : (which == 1) ? g_wk : g_wv;
    float* C = (which == 0) ? g_q : (which == 1) ? g_k : g_v;
    gemm_core(g_x, W, C, blockIdx.y * 128, n0, dsm);
}

// O projection (ctx is tf32-exact via attention epilogue).
__global__ __launch_bounds__(256, 2) void gemm_o(float* __restrict__ out) {
    extern __shared__ __align__(16) uint32_t dsm[];
    gemm_core(g_ctx, g_wo, out, blockIdx.y * 128, blockIdx.x * 128, dsm);
}

// ---------------------------------------------------------------------------
// RoPE, interleaved, rotation by -theta (verified Round 9).
// ---------------------------------------------------------------------------
__global__ __launch_bounds__(256) void rope_kernel() {
    int idx = blockIdx.x * 256 + threadIdx.x;
    int j = idx & 31;
    int h = (idx >> 5) & 15;
    int s = (idx >> 9) & 2047;
    int b = idx >> 20;

    float inv_freq = powf(10000.0f, -((float)(2 * j)) / 64.0f);
    float angle = (float)s * inv_freq;
    float c, sn;
    sincosf(angle, &c, &sn);

    size_t base = ((size_t)(b * SS + s)) * DD + h * DK + 2 * j;

    float q1 = g_q[base], q2 = g_q[base + 1];
    g_q[base]     = q1 * c + q2 * sn;
    g_q[base + 1] = -q1 * sn + q2 * c;

    float k1 = g_k[base], k2 = g_k[base + 1];
    g_k[base]     = k1 * c + k2 * sn;
    g_k[base + 1] = -k1 * sn + k2 * c;
}

// ---------------------------------------------------------------------------
// Tensor-core flash attention (tf32 MMA) — Round 11 version; epilogue now
// rounds ctx to tf32-exact (same rounding gemm staging used to do).
// ---------------------------------------------------------------------------
#define AP 68

__global__ __launch_bounds__(256) void attn_tc() {
    extern __shared__ __align__(16) uint32_t smu[];
    uint32_t* Ps = smu;
    uint32_t* Ks = Ps + 128 * AP;
    uint32_t* Vt = Ks + 64 * AP;

    const int tid  = threadIdx.x;
    const int w    = tid >> 5;
    const int lane = tid & 31;
    const int g    = lane >> 2;
    const int tg   = lane & 3;
    const int w16  = w * 16;

    const int qt = blockIdx.x, h = blockIdx.y, b = blockIdx.z;
    const int q0 = qt * 128;
    const size_t base_bh = (size_t)b * SS * DD + h * DK;
    const float scale = 0.125f;

    for (int i = tid; i < 128 * 16; i += 256) {
        int r  = i >> 4;
        int c4 = (i & 15) << 2;
        float4 val = *(const float4*)(g_q + base_bh + (size_t)(q0 + r) * DD + c4);
        uint32_t* p = &Ps[r * AP + c4];
        p[0] = f2tf32(val.x); p[1] = f2tf32(val.y);
        p[2] = f2tf32(val.z); p[3] = f2tf32(val.w);
    }
    __syncthreads();

    uint32_t aq[8][4];
#pragma unroll
    for (int ks = 0; ks < 8; ks++) {
        aq[ks][0] = Ps[(w16 + g) * AP + ks * 8 + tg];
        aq[ks][1] = Ps[(w16 + g + 8) * AP + ks * 8 + tg];
        aq[ks][2] = Ps[(w16 + g) * AP + ks * 8 + tg + 4];
        aq[ks][3] = Ps[(w16 + g + 8) * AP + ks * 8 + tg + 4];
    }

    float m0 = -INFINITY, m1 = -INFINITY, l0 = 0.0f, l1 = 0.0f;
    float o[8][4];
#pragma unroll
    for (int nt = 0; nt < 8; nt++)
#pragma unroll
        for (int i = 0; i < 4; i++) o[nt][i] = 0.0f;

    const int row_lo = q0 + w16;
    const int row_hi = row_lo + 15;
    const int ktmax  = 2 * qt + 1;

    for (int kt = 0; kt <= ktmax; kt++) {
        const int k0 = kt * 64;
        __syncthreads();
        for (int i = tid; i < 64 * 16; i += 256) {
            int c  = i >> 4;
            int d4 = (i & 15) << 2;
            float4 kv = *(const float4*)(g_k + base_bh + (size_t)(k0 + c) * DD + d4);
            uint32_t* pk = &Ks[c * AP + d4];
            pk[0] = f2tf32(kv.x); pk[1] = f2tf32(kv.y);
            pk[2] = f2tf32(kv.z); pk[3] = f2tf32(kv.w);
            float4 vv = *(const float4*)(g_v + base_bh + (size_t)(k0 + c) * DD + d4);
            Vt[(d4 + 0) * AP + c] = f2tf32(vv.x);
            Vt[(d4 + 1) * AP + c] = f2tf32(vv.y);
            Vt[(d4 + 2) * AP + c] = f2tf32(vv.z);
            Vt[(d4 + 3) * AP + c] = f2tf32(vv.w);
        }
        __syncthreads();

        if (k0 > row_hi) continue;

        float s[8][4];
#pragma unroll
        for (int nt = 0; nt < 8; nt++)
#pragma unroll
            for (int i = 0; i < 4; i++) s[nt][i] = 0.0f;

#pragma unroll
        for (int ks = 0; ks < 8; ks++) {
#pragma unroll
            for (int nt = 0; nt < 8; nt++) {
                uint32_t b0 = Ks[(nt * 8 + g) * AP + ks * 8 + tg];
                uint32_t b1 = Ks[(nt * 8 + g) * AP + ks * 8 + tg + 4];
                mma_tf32(s[nt], aq[ks], b0, b1);
            }
        }

        const bool full = (k0 + 63 <= row_lo);
#pragma unroll
        for (int nt = 0; nt < 8; nt++) {
#pragma unroll
            for (int i = 0; i < 4; i++) {
                float val = s[nt][i] * scale;
                if (!full) {
                    int col = k0 + nt * 8 + 2 * tg + (i & 1);
                    int row = row_lo + g + ((i & 2) ? 8 : 0);
                    if (col > row) val = -INFINITY;
                }
                s[nt][i] = val;
            }
        }

        float r0 = -INFINITY, r1 = -INFINITY;
#pragma unroll
        for (int nt = 0; nt < 8; nt++) {
            r0 = fmaxf(r0, fmaxf(s[nt][0], s[nt][1]));
            r1 = fmaxf(r1, fmaxf(s[nt][2], s[nt][3]));
        }
        r0 = fmaxf(r0, __shfl_xor_sync(0xffffffffu, r0, 1));
        r0 = fmaxf(r0, __shfl_xor_sync(0xffffffffu, r0, 2));
        r1 = fmaxf(r1, __shfl_xor_sync(0xffffffffu, r1, 1));
        r1 = fmaxf(r1, __shfl_xor_sync(0xffffffffu, r1, 2));

        float mn0 = fmaxf(m0, r0), mn1 = fmaxf(m1, r1);
        float al0 = (m0 == -INFINITY) ? 0.0f : __expf(m0 - mn0);
        float al1 = (m1 == -INFINITY) ? 0.0f : __expf(m1 - mn1);

        float ps0 = 0.0f, ps1 = 0.0f;
#pragma unroll
        for (int nt = 0; nt < 8; nt++) {
            float p0 = __expf(s[nt][0] - mn0);
            float p1 = __expf(s[nt][1] - mn0);
            float p2 = __expf(s[nt][2] - mn1);
            float p3 = __expf(s[nt][3] - mn1);
            s[nt][0] = p0; s[nt][1] = p1; s[nt][2] = p2; s[nt][3] = p3;
            ps0 += p0 + p1;
            ps1 += p2 + p3;
        }
        ps0 += __shfl_xor_sync(0xffffffffu, ps0, 1);
        ps0 += __shfl_xor_sync(0xffffffffu, ps0, 2);
        ps1 += __shfl_xor_sync(0xffffffffu, ps1, 1);
        ps1 += __shfl_xor_sync(0xffffffffu, ps1, 2);

        l0 = l0 * al0 + ps0;
        l1 = l1 * al1 + ps1;
        m0 = mn0;
        m1 = mn1;

#pragma unroll
        for (int nt = 0; nt < 8; nt++) {
            o[nt][0] *= al0; o[nt][1] *= al0;
            o[nt][2] *= al1; o[nt][3] *= al1;
        }

#pragma unroll
        for (int nt = 0; nt < 8; nt++) {
            Ps[(w16 + g) * AP + nt * 8 + 2 * tg]         = f2tf32(s[nt][0]);
            Ps[(w16 + g) * AP + nt * 8 + 2 * tg + 1]     = f2tf32(s[nt][1]);
            Ps[(w16 + g + 8) * AP + nt * 8 + 2 * tg]     = f2tf32(s[nt][2]);
            Ps[(w16 + g + 8) * AP + nt * 8 + 2 * tg + 1] = f2tf32(s[nt][3]);
        }
        __syncwarp();

#pragma unroll
        for (int ks = 0; ks < 8; ks++) {
            uint32_t ap[4];
            ap[0] = Ps[(w16 + g) * AP + ks * 8 + tg];
            ap[1] = Ps[(w16 + g + 8) * AP + ks * 8 + tg];
            ap[2] = Ps[(w16 + g) * AP + ks * 8 + tg + 4];
            ap[3] = Ps[(w16 + g + 8) * AP + ks * 8 + tg + 4];
#pragma unroll
            for (int nt = 0; nt < 8; nt++) {
                uint32_t b0 = Vt[(nt * 8 + g) * AP + ks * 8 + tg];
                uint32_t b1 = Vt[(nt * 8 + g) * AP + ks * 8 + tg + 4];
                mma_tf32(o[nt], ap, b0, b1);
            }
        }
        __syncwarp();
    }

    // Normalize, round to tf32-exact (gemm_o consumes raw), write ctx.
    const float inv0 = 1.0f / l0;
    const float inv1 = 1.0f / l1;
#pragma unroll
    for (int nt = 0; nt < 8; nt++) {
        int col = nt * 8 + 2 * tg;
        uint2 r0v = make_uint2(f2tf32(o[nt][0] * inv0), f2tf32(o[nt][1] * inv0));
        uint2 r1v = make_uint2(f2tf32(o[nt][2] * inv1), f2tf32(o[nt][3] * inv1));
        *(uint2*)(g_ctx + base_bh + (size_t)(q0 + w16 + g) * DD + col) = r0v;
        *(uint2*)(g_ctx + base_bh + (size_t)(q0 + w16 + g + 8) * DD + col) = r1v;
    }
}

// ---------------------------------------------------------------------------
extern "C" void kernel_launch(void* const* d_in, const int* in_sizes, int n_in,
                              void* d_out, int out_size) {
    const float* x  = (const float*)d_in[0];
    const float* wq = (const float*)d_in[1];
    const float* wk = (const float*)d_in[2];
    const float* wv = (const float*)d_in[3];
    const float* wo = (const float*)d_in[4];
    float* out = (float*)d_out;

    float *xr, *wqr, *wkr, *wvr, *wor;
    cudaGetSymbolAddress((void**)&xr,  g_x);
    cudaGetSymbolAddress((void**)&wqr, g_wq);
    cudaGetSymbolAddress((void**)&wkr, g_wk);
    cudaGetSymbolAddress((void**)&wvr, g_wv);
    cudaGetSymbolAddress((void**)&wor, g_wo);

    const int attn_smem = (128 * AP + 64 * AP + 64 * AP) * 4;  // 69632 bytes
    cudaFuncSetAttribute(attn_tc, cudaFuncAttributeMaxDynamicSharedMemorySize,
                         attn_smem);
    cudaFuncSetAttribute(gemm_qkv, cudaFuncAttributeMaxDynamicSharedMemorySize,
                         GEMM_SMEM);
    cudaFuncSetAttribute(gemm_o, cudaFuncAttributeMaxDynamicSharedMemorySize,
                         GEMM_SMEM);

    // Pre-round GEMM operands to tf32-exact fp32.
    tf32_round<<<(M_TOT * DD) / 1024, 256>>>(x, xr);
    tf32_round<<<(DD * DD) / 1024, 256>>>(wq, wqr);
    tf32_round<<<(DD * DD) / 1024, 256>>>(wk, wkr);
    tf32_round<<<(DD * DD) / 1024, 256>>>(wv, wvr);
    tf32_round<<<(DD * DD) / 1024, 256>>>(wo, wor);

    // Fused Q/K/V projections: 24 n-tiles x 64 m-tiles
    gemm_qkv<<<dim3(24, M_TOT / 128), 256, GEMM_SMEM>>>();

    rope_kernel<<<(BB * SS * HH * (DK / 2)) / 256, 256>>>();

    attn_tc<<<dim3(SS / 128, HH, BB), 256, attn_smem>>>();

    gemm_o<<<dim3(DD / 128, M_TOT / 128), 256, GEMM_SMEM>>>(out);
}

// round 16
// speedup vs baseline: 2.9142x; 1.0380x over previous
#include <cuda_runtime.h>
#include <math.h>
#include <stdint.h>

#define BB 4
#define SS 2048
#define DD 1024
#define HH 16
#define DK 64
#define M_TOT (BB * SS)

// Scratch buffers (allocation-free rule: __device__ globals)
__device__ float g_q[M_TOT * DD];
__device__ float g_k[M_TOT * DD];
__device__ float g_v[M_TOT * DD];
__device__ float g_ctx[M_TOT * DD];
// tf32-exact copies of GEMM operands
__device__ float g_x[M_TOT * DD];
__device__ float g_wq[DD * DD];
__device__ float g_wk[DD * DD];
__device__ float g_wv[DD * DD];
__device__ float g_wo[DD * DD];

__device__ __forceinline__ uint32_t f2tf32(float x) {
    uint32_t r;
    asm("cvt.rna.tf32.f32 %0, %1;" : "=r"(r) : "f"(x));
    return r;
}

__device__ __forceinline__ void mma_tf32(float* c, const uint32_t* a,
                                         uint32_t b0, uint32_t b1) {
    asm volatile(
        "mma.sync.aligned.m16n8k8.row.col.f32.tf32.tf32.f32 "
        "{%0,%1,%2,%3}, {%4,%5,%6,%7}, {%8,%9}, {%0,%1,%2,%3};\n"
        : "+f"(c[0]), "+f"(c[1]), "+f"(c[2]), "+f"(c[3])
        : "r"(a[0]), "r"(a[1]), "r"(a[2]), "r"(a[3]), "r"(b0), "r"(b1));
}

// ---- cp.async helpers -----------------------------------------------------
__device__ __forceinline__ void cpa16(void* smem_ptr, const void* gptr) {
    uint32_t sa = (uint32_t)__cvta_generic_to_shared(smem_ptr);
    asm volatile("cp.async.cg.shared.global [%0], [%1], 16;\n"
                 :: "r"(sa), "l"(gptr));
}
#define CP_COMMIT() asm volatile("cp.async.commit_group;\n" ::: "memory")
#define CP_WAIT0()  asm volatile("cp.async.wait_group 0;\n" ::: "memory")
#define CP_WAIT1()  asm volatile("cp.async.wait_group 1;\n" ::: "memory")

// ---------------------------------------------------------------------------
// tf32 pre-rounding pass: out[i] = RNA_tf32(in[i])  (in-place safe)
// ---------------------------------------------------------------------------
__global__ __launch_bounds__(256) void tf32_round(const float* __restrict__ in,
                                                  float* __restrict__ out) {
    int i = (blockIdx.x * 256 + threadIdx.x) * 4;
    float4 v = *(const float4*)(in + i);
    uint4 r;
    r.x = f2tf32(v.x); r.y = f2tf32(v.y);
    r.z = f2tf32(v.z); r.w = f2tf32(v.w);
    *(uint4*)(out + i) = r;
}

// ---------------------------------------------------------------------------
// TF32 GEMM core (R13, validated): C[m][n] = sum_k A[m][k] * W[n][k]
// A, W must be tf32-exact. cp.async 2-stage pipeline, one wait + one sync
// per 32-k tile. Block tile 128x128, 8 warps (4m x 2n), warp tile 32x64.
// ---------------------------------------------------------------------------
#define KP 36
#define BUFW (128 * KP)
#define GEMM_SMEM (4 * BUFW * 4)   // 73728 bytes

__device__ __forceinline__ void gemm_core(const float* __restrict__ A,
                                          const float* __restrict__ W,
                                          float* __restrict__ C,
                                          int m0, int n0, uint32_t* dsm) {
    uint32_t* As = dsm;              // [2][128][KP]
    uint32_t* Bs = dsm + 2 * BUFW;   // [2][128][KP]

    const int tid  = threadIdx.x;
    const int warp = tid >> 5;
    const int lane = tid & 31;
    const int wm = (warp & 3) * 32;
    const int wn = (warp >> 2) * 64;
    const int g  = lane >> 2;
    const int tg = lane & 3;

    int rr[4], cc[4];
#pragma unroll
    for (int l = 0; l < 4; l++) {
        int idx = l * 256 + tid;
        rr[l] = idx >> 3;
        cc[l] = (idx & 7) << 2;
    }

    float acc[2][8][4];
#pragma unroll
    for (int mt = 0; mt < 2; mt++)
#pragma unroll
        for (int nt = 0; nt < 8; nt++)
#pragma unroll
            for (int i = 0; i < 4; i++) acc[mt][nt][i] = 0.0f;

#pragma unroll
    for (int l = 0; l < 4; l++) {
        cpa16(&As[rr[l] * KP + cc[l]], A + (size_t)(m0 + rr[l]) * DD + cc[l]);
        cpa16(&Bs[rr[l] * KP + cc[l]], W + (size_t)(n0 + rr[l]) * DD + cc[l]);
    }
    CP_COMMIT();

    for (int kt = 0; kt < 32; kt++) {
        CP_WAIT0();
        __syncthreads();

        if (kt < 31) {
            const int k0 = (kt + 1) * 32;
            uint32_t* An = As + ((kt + 1) & 1) * BUFW;
            uint32_t* Bn = Bs + ((kt + 1) & 1) * BUFW;
#pragma unroll
            for (int l = 0; l < 4; l++) {
                cpa16(&An[rr[l] * KP + cc[l]],
                      A + (size_t)(m0 + rr[l]) * DD + k0 + cc[l]);
                cpa16(&Bn[rr[l] * KP + cc[l]],
                      W + (size_t)(n0 + rr[l]) * DD + k0 + cc[l]);
            }
            CP_COMMIT();
        }

        const uint32_t* Ac = As + (kt & 1) * BUFW;
        const uint32_t* Bc = Bs + (kt & 1) * BUFW;

#pragma unroll
        for (int ks = 0; ks < 32; ks += 8) {
            uint32_t a[2][4];
#pragma unroll
            for (int mt = 0; mt < 2; mt++) {
                int mr = wm + mt * 16;
                a[mt][0] = Ac[(mr + g) * KP + ks + tg];
                a[mt][1] = Ac[(mr + g + 8) * KP + ks + tg];
                a[mt][2] = Ac[(mr + g) * KP + ks + tg + 4];
                a[mt][3] = Ac[(mr + g + 8) * KP + ks + tg + 4];
            }
#pragma unroll
            for (int nt = 0; nt < 8; nt++) {
                int nc = wn + nt * 8;
                uint32_t b0 = Bc[(nc + g) * KP + ks + tg];
                uint32_t b1 = Bc[(nc + g) * KP + ks + tg + 4];
#pragma unroll
                for (int mt = 0; mt < 2; mt++)
                    mma_tf32(acc[mt][nt], a[mt], b0, b1);
            }
        }
    }

#pragma unroll
    for (int mt = 0; mt < 2; mt++) {
        int row = m0 + wm + mt * 16;
#pragma unroll
        for (int nt = 0; nt < 8; nt++) {
            int col = n0 + wn + nt * 8 + 2 * tg;
            *(float2*)(C + (size_t)(row + g) * DD + col) =
                make_float2(acc[mt][nt][0], acc[mt][nt][1]);
            *(float2*)(C + (size_t)(row + g + 8) * DD + col) =
                make_float2(acc[mt][nt][2], acc[mt][nt][3]);
        }
    }
}

__global__ __launch_bounds__(256, 2) void gemm_qkv() {
    extern __shared__ __align__(16) uint32_t dsm[];
    const int which = blockIdx.x >> 3;
    const int n0 = (blockIdx.x & 7) * 128;
    const float* W = (which == 0) ? g_wq : (which == 1) ? g_wk : g_wv;
    float* C = (which == 0) ? g_q : (which == 1) ? g_k : g_v;
    gemm_core(g_x, W, C, blockIdx.y * 128, n0, dsm);
}

__global__ __launch_bounds__(256, 2) void gemm_o(float* __restrict__ out) {
    extern __shared__ __align__(16) uint32_t dsm[];
    gemm_core(g_ctx, g_wo, out, blockIdx.y * 128, blockIdx.x * 128, dsm);
}

// ---------------------------------------------------------------------------
// RoPE, interleaved, rotation by -theta (verified Round 9).
// NOW writes tf32-exact bits (same value attention staged before — the
// rounding point moved from consumer to producer; bit-identical downstream).
// ---------------------------------------------------------------------------
__global__ __launch_bounds__(256) void rope_kernel() {
    int idx = blockIdx.x * 256 + threadIdx.x;
    int j = idx & 31;
    int h = (idx >> 5) & 15;
    int s = (idx >> 9) & 2047;
    int b = idx >> 20;

    float inv_freq = powf(10000.0f, -((float)(2 * j)) / 64.0f);
    float angle = (float)s * inv_freq;
    float c, sn;
    sincosf(angle, &c, &sn);

    size_t base = ((size_t)(b * SS + s)) * DD + h * DK + 2 * j;

    float q1 = g_q[base], q2 = g_q[base + 1];
    ((uint32_t*)g_q)[base]     = f2tf32(q1 * c + q2 * sn);
    ((uint32_t*)g_q)[base + 1] = f2tf32(-q1 * sn + q2 * c);

    float k1 = g_k[base], k2 = g_k[base + 1];
    ((uint32_t*)g_k)[base]     = f2tf32(k1 * c + k2 * sn);
    ((uint32_t*)g_k)[base + 1] = f2tf32(-k1 * sn + k2 * c);
}

// ---------------------------------------------------------------------------
// Tensor-core flash attention (tf32 legacy MMA). q/k/v are tf32-exact in
// GMEM, so staging is raw copies: Q and K via cp.async, V transpose via
// raw float4 -> 4x STS (no cvt anywhere on the staging path).
// ---------------------------------------------------------------------------
#define AP 68

__global__ __launch_bounds__(256) void attn_tc() {
    extern __shared__ __align__(16) uint32_t smu[];
    uint32_t* Ps = smu;
    uint32_t* Ks = Ps + 128 * AP;
    uint32_t* Vt = Ks + 64 * AP;

    const int tid  = threadIdx.x;
    const int w    = tid >> 5;
    const int lane = tid & 31;
    const int g    = lane >> 2;
    const int tg   = lane & 3;
    const int w16  = w * 16;

    const int qt = blockIdx.x, h = blockIdx.y, b = blockIdx.z;
    const int q0 = qt * 128;
    const size_t base_bh = (size_t)b * SS * DD + h * DK;
    const float scale = 0.125f;

    // ---- Stage Q (raw, cp.async) ----
    for (int i = tid; i < 128 * 16; i += 256) {
        int r  = i >> 4;
        int c4 = (i & 15) << 2;
        cpa16(&Ps[r * AP + c4], g_q + base_bh + (size_t)(q0 + r) * DD + c4);
    }
    CP_COMMIT();
    CP_WAIT0();
    __syncthreads();

    uint32_t aq[8][4];
#pragma unroll
    for (int ks = 0; ks < 8; ks++) {
        aq[ks][0] = Ps[(w16 + g) * AP + ks * 8 + tg];
        aq[ks][1] = Ps[(w16 + g + 8) * AP + ks * 8 + tg];
        aq[ks][2] = Ps[(w16 + g) * AP + ks * 8 + tg + 4];
        aq[ks][3] = Ps[(w16 + g + 8) * AP + ks * 8 + tg + 4];
    }

    float m0 = -INFINITY, m1 = -INFINITY, l0 = 0.0f, l1 = 0.0f;
    float o[8][4];
#pragma unroll
    for (int nt = 0; nt < 8; nt++)
#pragma unroll
        for (int i = 0; i < 4; i++) o[nt][i] = 0.0f;

    const int row_lo = q0 + w16;
    const int row_hi = row_lo + 15;
    const int ktmax  = 2 * qt + 1;

    for (int kt = 0; kt <= ktmax; kt++) {
        const int k0 = kt * 64;
        __syncthreads();
        // K tile: raw cp.async into natural [c][d]
        for (int i = tid; i < 64 * 16; i += 256) {
            int c  = i >> 4;
            int d4 = (i & 15) << 2;
            cpa16(&Ks[c * AP + d4], g_k + base_bh + (size_t)(k0 + c) * DD + d4);
        }
        CP_COMMIT();
        // V tile: raw transposed staging [d][c] (no cvt)
        for (int i = tid; i < 64 * 16; i += 256) {
            int c  = i >> 4;
            int d4 = (i & 15) << 2;
            uint4 vv = *(const uint4*)(g_v + base_bh + (size_t)(k0 + c) * DD + d4);
            Vt[(d4 + 0) * AP + c] = vv.x;
            Vt[(d4 + 1) * AP + c] = vv.y;
            Vt[(d4 + 2) * AP + c] = vv.z;
            Vt[(d4 + 3) * AP + c] = vv.w;
        }
        CP_WAIT0();
        __syncthreads();

        if (k0 > row_hi) continue;

        float s[8][4];
#pragma unroll
        for (int nt = 0; nt < 8; nt++)
#pragma unroll
            for (int i = 0; i < 4; i++) s[nt][i] = 0.0f;

#pragma unroll
        for (int ks = 0; ks < 8; ks++) {
#pragma unroll
            for (int nt = 0; nt < 8; nt++) {
                uint32_t b0 = Ks[(nt * 8 + g) * AP + ks * 8 + tg];
                uint32_t b1 = Ks[(nt * 8 + g) * AP + ks * 8 + tg + 4];
                mma_tf32(s[nt], aq[ks], b0, b1);
            }
        }

        const bool full = (k0 + 63 <= row_lo);
#pragma unroll
        for (int nt = 0; nt < 8; nt++) {
#pragma unroll
            for (int i = 0; i < 4; i++) {
                float val = s[nt][i] * scale;
                if (!full) {
                    int col = k0 + nt * 8 + 2 * tg + (i & 1);
                    int row = row_lo + g + ((i & 2) ? 8 : 0);
                    if (col > row) val = -INFINITY;
                }
                s[nt][i] = val;
            }
        }

        float r0 = -INFINITY, r1 = -INFINITY;
#pragma unroll
        for (int nt = 0; nt < 8; nt++) {
            r0 = fmaxf(r0, fmaxf(s[nt][0], s[nt][1]));
            r1 = fmaxf(r1, fmaxf(s[nt][2], s[nt][3]));
        }
        r0 = fmaxf(r0, __shfl_xor_sync(0xffffffffu, r0, 1));
        r0 = fmaxf(r0, __shfl_xor_sync(0xffffffffu, r0, 2));
        r1 = fmaxf(r1, __shfl_xor_sync(0xffffffffu, r1, 1));
        r1 = fmaxf(r1, __shfl_xor_sync(0xffffffffu, r1, 2));

        float mn0 = fmaxf(m0, r0), mn1 = fmaxf(m1, r1);
        float al0 = (m0 == -INFINITY) ? 0.0f : __expf(m0 - mn0);
        float al1 = (m1 == -INFINITY) ? 0.0f : __expf(m1 - mn1);

        float ps0 = 0.0f, ps1 = 0.0f;
#pragma unroll
        for (int nt = 0; nt < 8; nt++) {
            float p0 = __expf(s[nt][0] - mn0);
            float p1 = __expf(s[nt][1] - mn0);
            float p2 = __expf(s[nt][2] - mn1);
            float p3 = __expf(s[nt][3] - mn1);
            s[nt][0] = p0; s[nt][1] = p1; s[nt][2] = p2; s[nt][3] = p3;
            ps0 += p0 + p1;
            ps1 += p2 + p3;
        }
        ps0 += __shfl_xor_sync(0xffffffffu, ps0, 1);
        ps0 += __shfl_xor_sync(0xffffffffu, ps0, 2);
        ps1 += __shfl_xor_sync(0xffffffffu, ps1, 1);
        ps1 += __shfl_xor_sync(0xffffffffu, ps1, 2);

        l0 = l0 * al0 + ps0;
        l1 = l1 * al1 + ps1;
        m0 = mn0;
        m1 = mn1;

#pragma unroll
        for (int nt = 0; nt < 8; nt++) {
            o[nt][0] *= al0; o[nt][1] *= al0;
            o[nt][2] *= al1; o[nt][3] *= al1;
        }

#pragma unroll
        for (int nt = 0; nt < 8; nt++) {
            Ps[(w16 + g) * AP + nt * 8 + 2 * tg]         = f2tf32(s[nt][0]);
            Ps[(w16 + g) * AP + nt * 8 + 2 * tg + 1]     = f2tf32(s[nt][1]);
            Ps[(w16 + g + 8) * AP + nt * 8 + 2 * tg]     = f2tf32(s[nt][2]);
            Ps[(w16 + g + 8) * AP + nt * 8 + 2 * tg + 1] = f2tf32(s[nt][3]);
        }
        __syncwarp();

#pragma unroll
        for (int ks = 0; ks < 8; ks++) {
            uint32_t ap[4];
            ap[0] = Ps[(w16 + g) * AP + ks * 8 + tg];
            ap[1] = Ps[(w16 + g + 8) * AP + ks * 8 + tg];
            ap[2] = Ps[(w16 + g) * AP + ks * 8 + tg + 4];
            ap[3] = Ps[(w16 + g + 8) * AP + ks * 8 + tg + 4];
#pragma unroll
            for (int nt = 0; nt < 8; nt++) {
                uint32_t b0 = Vt[(nt * 8 + g) * AP + ks * 8 + tg];
                uint32_t b1 = Vt[(nt * 8 + g) * AP + ks * 8 + tg + 4];
                mma_tf32(o[nt], ap, b0, b1);
            }
        }
        __syncwarp();
    }

    // Normalize, round to tf32-exact (gemm_o consumes raw), write ctx.
    const float inv0 = 1.0f / l0;
    const float inv1 = 1.0f / l1;
#pragma unroll
    for (int nt = 0; nt < 8; nt++) {
        int col = nt * 8 + 2 * tg;
        uint2 r0v = make_uint2(f2tf32(o[nt][0] * inv0), f2tf32(o[nt][1] * inv0));
        uint2 r1v = make_uint2(f2tf32(o[nt][2] * inv1), f2tf32(o[nt][3] * inv1));
        *(uint2*)(g_ctx + base_bh + (size_t)(q0 + w16 + g) * DD + col) = r0v;
        *(uint2*)(g_ctx + base_bh + (size_t)(q0 + w16 + g + 8) * DD + col) = r1v;
    }
}

// ---------------------------------------------------------------------------
extern "C" void kernel_launch(void* const* d_in, const int* in_sizes, int n_in,
                              void* d_out, int out_size) {
    const float* x  = (const float*)d_in[0];
    const float* wq = (const float*)d_in[1];
    const float* wk = (const float*)d_in[2];
    const float* wv = (const float*)d_in[3];
    const float* wo = (const float*)d_in[4];
    float* out = (float*)d_out;

    float *xr, *wqr, *wkr, *wvr, *wor, *v;
    cudaGetSymbolAddress((void**)&xr,  g_x);
    cudaGetSymbolAddress((void**)&wqr, g_wq);
    cudaGetSymbolAddress((void**)&wkr, g_wk);
    cudaGetSymbolAddress((void**)&wvr, g_wv);
    cudaGetSymbolAddress((void**)&wor, g_wo);
    cudaGetSymbolAddress((void**)&v,   g_v);

    const int attn_smem = (128 * AP + 64 * AP + 64 * AP) * 4;  // 69632 bytes
    cudaFuncSetAttribute(attn_tc, cudaFuncAttributeMaxDynamicSharedMemorySize,
                         attn_smem);
    cudaFuncSetAttribute(gemm_qkv, cudaFuncAttributeMaxDynamicSharedMemorySize,
                         GEMM_SMEM);
    cudaFuncSetAttribute(gemm_o, cudaFuncAttributeMaxDynamicSharedMemorySize,
                         GEMM_SMEM);

    // Pre-round GEMM operands to tf32-exact fp32.
    tf32_round<<<(M_TOT * DD) / 1024, 256>>>(x, xr);
    tf32_round<<<(DD * DD) / 1024, 256>>>(wq, wqr);
    tf32_round<<<(DD * DD) / 1024, 256>>>(wk, wkr);
    tf32_round<<<(DD * DD) / 1024, 256>>>(wv, wvr);
    tf32_round<<<(DD * DD) / 1024, 256>>>(wo, wor);

    // Fused Q/K/V projections: 24 n-tiles x 64 m-tiles
    gemm_qkv<<<dim3(24, M_TOT / 128), 256, GEMM_SMEM>>>();

    // RoPE (writes tf32-exact q/k); round v in place for raw attention staging.
    rope_kernel<<<(BB * SS * HH * (DK / 2)) / 256, 256>>>();
    tf32_round<<<(M_TOT * DD) / 1024, 256>>>(v, v);

    attn_tc<<<dim3(SS / 128, HH, BB), 256, attn_smem>>>();

    gemm_o<<<dim3(DD / 128, M_TOT / 128), 256, GEMM_SMEM>>>(out);
}

// round 17
// speedup vs baseline: 2.9844x; 1.0241x over previous
#include <cuda_runtime.h>
#include <math.h>
#include <stdint.h>

#define BB 4
#define SS 2048
#define DD 1024
#define HH 16
#define DK 64
#define M_TOT (BB * SS)

// Scratch buffers (allocation-free rule: __device__ globals)
__device__ float g_q[M_TOT * DD];
__device__ float g_k[M_TOT * DD];
__device__ float g_v[M_TOT * DD];
__device__ float g_ctx[M_TOT * DD];
// tf32-exact copies of GEMM operands
__device__ float g_x[M_TOT * DD];
__device__ float g_wq[DD * DD];
__device__ float g_wk[DD * DD];
__device__ float g_wv[DD * DD];
__device__ float g_wo[DD * DD];

__device__ __forceinline__ uint32_t f2tf32(float x) {
    uint32_t r;
    asm("cvt.rna.tf32.f32 %0, %1;" : "=r"(r) : "f"(x));
    return r;
}

__device__ __forceinline__ void mma_tf32(float* c, const uint32_t* a,
                                         uint32_t b0, uint32_t b1) {
    asm volatile(
        "mma.sync.aligned.m16n8k8.row.col.f32.tf32.tf32.f32 "
        "{%0,%1,%2,%3}, {%4,%5,%6,%7}, {%8,%9}, {%0,%1,%2,%3};\n"
        : "+f"(c[0]), "+f"(c[1]), "+f"(c[2]), "+f"(c[3])
        : "r"(a[0]), "r"(a[1]), "r"(a[2]), "r"(a[3]), "r"(b0), "r"(b1));
}

// ---- cp.async helpers -----------------------------------------------------
__device__ __forceinline__ void cpa16(void* smem_ptr, const void* gptr) {
    uint32_t sa = (uint32_t)__cvta_generic_to_shared(smem_ptr);
    asm volatile("cp.async.cg.shared.global [%0], [%1], 16;\n"
                 :: "r"(sa), "l"(gptr));
}
#define CP_COMMIT() asm volatile("cp.async.commit_group;\n" ::: "memory")
#define CP_WAIT0()  asm volatile("cp.async.wait_group 0;\n" ::: "memory")

// ---------------------------------------------------------------------------
// tf32 pre-rounding pass: out[i] = RNA_tf32(in[i])  (in-place safe)
// ---------------------------------------------------------------------------
__global__ __launch_bounds__(256) void tf32_round(const float* __restrict__ in,
                                                  float* __restrict__ out) {
    int i = (blockIdx.x * 256 + threadIdx.x) * 4;
    float4 v = *(const float4*)(in + i);
    uint4 r;
    r.x = f2tf32(v.x); r.y = f2tf32(v.y);
    r.z = f2tf32(v.z); r.w = f2tf32(v.w);
    *(uint4*)(out + i) = r;
}

// ---------------------------------------------------------------------------
// TF32 GEMM core (R13, validated): C[m][n] = sum_k A[m][k] * W[n][k]
// ---------------------------------------------------------------------------
#define KP 36
#define BUFW (128 * KP)
#define GEMM_SMEM (4 * BUFW * 4)   // 73728 bytes

__device__ __forceinline__ void gemm_core(const float* __restrict__ A,
                                          const float* __restrict__ W,
                                          float* __restrict__ C,
                                          int m0, int n0, uint32_t* dsm) {
    uint32_t* As = dsm;
    uint32_t* Bs = dsm + 2 * BUFW;

    const int tid  = threadIdx.x;
    const int warp = tid >> 5;
    const int lane = tid & 31;
    const int wm = (warp & 3) * 32;
    const int wn = (warp >> 2) * 64;
    const int g  = lane >> 2;
    const int tg = lane & 3;

    int rr[4], cc[4];
#pragma unroll
    for (int l = 0; l < 4; l++) {
        int idx = l * 256 + tid;
        rr[l] = idx >> 3;
        cc[l] = (idx & 7) << 2;
    }

    float acc[2][8][4];
#pragma unroll
    for (int mt = 0; mt < 2; mt++)
#pragma unroll
        for (int nt = 0; nt < 8; nt++)
#pragma unroll
            for (int i = 0; i < 4; i++) acc[mt][nt][i] = 0.0f;

#pragma unroll
    for (int l = 0; l < 4; l++) {
        cpa16(&As[rr[l] * KP + cc[l]], A + (size_t)(m0 + rr[l]) * DD + cc[l]);
        cpa16(&Bs[rr[l] * KP + cc[l]], W + (size_t)(n0 + rr[l]) * DD + cc[l]);
    }
    CP_COMMIT();

    for (int kt = 0; kt < 32; kt++) {
        CP_WAIT0();
        __syncthreads();

        if (kt < 31) {
            const int k0 = (kt + 1) * 32;
            uint32_t* An = As + ((kt + 1) & 1) * BUFW;
            uint32_t* Bn = Bs + ((kt + 1) & 1) * BUFW;
#pragma unroll
            for (int l = 0; l < 4; l++) {
                cpa16(&An[rr[l] * KP + cc[l]],
                      A + (size_t)(m0 + rr[l]) * DD + k0 + cc[l]);
                cpa16(&Bn[rr[l] * KP + cc[l]],
                      W + (size_t)(n0 + rr[l]) * DD + k0 + cc[l]);
            }
            CP_COMMIT();
        }

        const uint32_t* Ac = As + (kt & 1) * BUFW;
        const uint32_t* Bc = Bs + (kt & 1) * BUFW;

#pragma unroll
        for (int ks = 0; ks < 32; ks += 8) {
            uint32_t a[2][4];
#pragma unroll
            for (int mt = 0; mt < 2; mt++) {
                int mr = wm + mt * 16;
                a[mt][0] = Ac[(mr + g) * KP + ks + tg];
                a[mt][1] = Ac[(mr + g + 8) * KP + ks + tg];
                a[mt][2] = Ac[(mr + g) * KP + ks + tg + 4];
                a[mt][3] = Ac[(mr + g + 8) * KP + ks + tg + 4];
            }
#pragma unroll
            for (int nt = 0; nt < 8; nt++) {
                int nc = wn + nt * 8;
                uint32_t b0 = Bc[(nc + g) * KP + ks + tg];
                uint32_t b1 = Bc[(nc + g) * KP + ks + tg + 4];
#pragma unroll
                for (int mt = 0; mt < 2; mt++)
                    mma_tf32(acc[mt][nt], a[mt], b0, b1);
            }
        }
    }

#pragma unroll
    for (int mt = 0; mt < 2; mt++) {
        int row = m0 + wm + mt * 16;
#pragma unroll
        for (int nt = 0; nt < 8; nt++) {
            int col = n0 + wn + nt * 8 + 2 * tg;
            *(float2*)(C + (size_t)(row + g) * DD + col) =
                make_float2(acc[mt][nt][0], acc[mt][nt][1]);
            *(float2*)(C + (size_t)(row + g + 8) * DD + col) =
                make_float2(acc[mt][nt][2], acc[mt][nt][3]);
        }
    }
}

__global__ __launch_bounds__(256, 2) void gemm_qkv() {
    extern __shared__ __align__(16) uint32_t dsm[];
    const int which = blockIdx.x >> 3;
    const int n0 = (blockIdx.x & 7) * 128;
    const float* W = (which == 0) ? g_wq : (which == 1) ? g_wk : g_wv;
    float* C = (which == 0) ? g_q : (which == 1) ? g_k : g_v;
    gemm_core(g_x, W, C, blockIdx.y * 128, n0, dsm);
}

__global__ __launch_bounds__(256, 2) void gemm_o(float* __restrict__ out) {
    extern __shared__ __align__(16) uint32_t dsm[];
    gemm_core(g_ctx, g_wo, out, blockIdx.y * 128, blockIdx.x * 128, dsm);
}

// ---------------------------------------------------------------------------
// RoPE, interleaved, rotation by -theta; writes tf32-exact bits.
// ---------------------------------------------------------------------------
__global__ __launch_bounds__(256) void rope_kernel() {
    int idx = blockIdx.x * 256 + threadIdx.x;
    int j = idx & 31;
    int h = (idx >> 5) & 15;
    int s = (idx >> 9) & 2047;
    int b = idx >> 20;

    float inv_freq = powf(10000.0f, -((float)(2 * j)) / 64.0f);
    float angle = (float)s * inv_freq;
    float c, sn;
    sincosf(angle, &c, &sn);

    size_t base = ((size_t)(b * SS + s)) * DD + h * DK + 2 * j;

    float q1 = g_q[base], q2 = g_q[base + 1];
    ((uint32_t*)g_q)[base]     = f2tf32(q1 * c + q2 * sn);
    ((uint32_t*)g_q)[base + 1] = f2tf32(-q1 * sn + q2 * c);

    float k1 = g_k[base], k2 = g_k[base + 1];
    ((uint32_t*)g_k)[base]     = f2tf32(k1 * c + k2 * sn);
    ((uint32_t*)g_k)[base + 1] = f2tf32(-k1 * sn + k2 * c);
}

// ---------------------------------------------------------------------------
// Tensor-core flash attention (tf32 legacy MMA), K/V DOUBLE-BUFFERED:
// iteration kt waits tile kt, syncs once, issues staging of kt+1 into the
// alternate buffer, then computes tile kt. V-transpose LDG/STS of kt+1
// overlaps MMA+softmax of kt; STS visibility via the top-of-loop BAR.
// ---------------------------------------------------------------------------
#define AP 68
#define KVW (64 * AP)                 // one K or V buffer (words)
#define ATTN_SMEM ((128 * AP + 4 * KVW) * 4)   // 104448 bytes

__global__ __launch_bounds__(256) void attn_tc() {
    extern __shared__ __align__(16) uint32_t smu[];
    uint32_t* Ps = smu;                       // [128][AP] Q staging / P tiles
    uint32_t* Ks = Ps + 128 * AP;             // [2][64][AP] K, natural [c][d]
    uint32_t* Vt = Ks + 2 * KVW;              // [2][64][AP] V, transposed [d][c]

    const int tid  = threadIdx.x;
    const int w    = tid >> 5;
    const int lane = tid & 31;
    const int g    = lane >> 2;
    const int tg   = lane & 3;
    const int w16  = w * 16;

    const int qt = blockIdx.x, h = blockIdx.y, b = blockIdx.z;
    const int q0 = qt * 128;
    const size_t base_bh = (size_t)b * SS * DD + h * DK;
    const float scale = 0.125f;

    // ---- Prologue: stage Q (cp.async) + K tile 0 (cp.async) + V tile 0 ----
    for (int i = tid; i < 128 * 16; i += 256) {
        int r  = i >> 4;
        int c4 = (i & 15) << 2;
        cpa16(&Ps[r * AP + c4], g_q + base_bh + (size_t)(q0 + r) * DD + c4);
    }
    for (int i = tid; i < 64 * 16; i += 256) {
        int c  = i >> 4;
        int d4 = (i & 15) << 2;
        cpa16(&Ks[c * AP + d4], g_k + base_bh + (size_t)c * DD + d4);
    }
    CP_COMMIT();
    for (int i = tid; i < 64 * 16; i += 256) {
        int c  = i >> 4;
        int d4 = (i & 15) << 2;
        uint4 vv = *(const uint4*)(g_v + base_bh + (size_t)c * DD + d4);
        Vt[(d4 + 0) * AP + c] = vv.x;
        Vt[(d4 + 1) * AP + c] = vv.y;
        Vt[(d4 + 2) * AP + c] = vv.z;
        Vt[(d4 + 3) * AP + c] = vv.w;
    }
    CP_WAIT0();
    __syncthreads();

    uint32_t aq[8][4];
#pragma unroll
    for (int ks = 0; ks < 8; ks++) {
        aq[ks][0] = Ps[(w16 + g) * AP + ks * 8 + tg];
        aq[ks][1] = Ps[(w16 + g + 8) * AP + ks * 8 + tg];
        aq[ks][2] = Ps[(w16 + g) * AP + ks * 8 + tg + 4];
        aq[ks][3] = Ps[(w16 + g + 8) * AP + ks * 8 + tg + 4];
    }

    float m0 = -INFINITY, m1 = -INFINITY, l0 = 0.0f, l1 = 0.0f;
    float o[8][4];
#pragma unroll
    for (int nt = 0; nt < 8; nt++)
#pragma unroll
        for (int i = 0; i < 4; i++) o[nt][i] = 0.0f;

    const int row_lo = q0 + w16;
    const int row_hi = row_lo + 15;
    const int ktmax  = 2 * qt + 1;

    for (int kt = 0; kt <= ktmax; kt++) {
        const int k0 = kt * 64;
        if (kt > 0) {            // tile kt staged in iteration kt-1
            CP_WAIT0();          // K cp.async complete
            __syncthreads();     // V STS visible; prior reads of buf kt&1 done
        }

        // ---- Issue staging of tile kt+1 into the alternate buffer ----
        if (kt < ktmax) {
            const int kn0 = (kt + 1) * 64;
            uint32_t* Kn = Ks + ((kt + 1) & 1) * KVW;
            uint32_t* Vn = Vt + ((kt + 1) & 1) * KVW;
            for (int i = tid; i < 64 * 16; i += 256) {
                int c  = i >> 4;
                int d4 = (i & 15) << 2;
                cpa16(&Kn[c * AP + d4],
                      g_k + base_bh + (size_t)(kn0 + c) * DD + d4);
            }
            CP_COMMIT();
            for (int i = tid; i < 64 * 16; i += 256) {
                int c  = i >> 4;
                int d4 = (i & 15) << 2;
                uint4 vv = *(const uint4*)(g_v + base_bh + (size_t)(kn0 + c) * DD + d4);
                Vn[(d4 + 0) * AP + c] = vv.x;
                Vn[(d4 + 1) * AP + c] = vv.y;
                Vn[(d4 + 2) * AP + c] = vv.z;
                Vn[(d4 + 3) * AP + c] = vv.w;
            }
        }

        if (k0 > row_hi) continue;   // causal: tile above this warp's rows

        const uint32_t* Kc = Ks + (kt & 1) * KVW;
        const uint32_t* Vc = Vt + (kt & 1) * KVW;

        float s[8][4];
#pragma unroll
        for (int nt = 0; nt < 8; nt++)
#pragma unroll
            for (int i = 0; i < 4; i++) s[nt][i] = 0.0f;

#pragma unroll
        for (int ks = 0; ks < 8; ks++) {
#pragma unroll
            for (int nt = 0; nt < 8; nt++) {
                uint32_t b0 = Kc[(nt * 8 + g) * AP + ks * 8 + tg];
                uint32_t b1 = Kc[(nt * 8 + g) * AP + ks * 8 + tg + 4];
                mma_tf32(s[nt], aq[ks], b0, b1);
            }
        }

        const bool full = (k0 + 63 <= row_lo);
#pragma unroll
        for (int nt = 0; nt < 8; nt++) {
#pragma unroll
            for (int i = 0; i < 4; i++) {
                float val = s[nt][i] * scale;
                if (!full) {
                    int col = k0 + nt * 8 + 2 * tg + (i & 1);
                    int row = row_lo + g + ((i & 2) ? 8 : 0);
                    if (col > row) val = -INFINITY;
                }
                s[nt][i] = val;
            }
        }

        float r0 = -INFINITY, r1 = -INFINITY;
#pragma unroll
        for (int nt = 0; nt < 8; nt++) {
            r0 = fmaxf(r0, fmaxf(s[nt][0], s[nt][1]));
            r1 = fmaxf(r1, fmaxf(s[nt][2], s[nt][3]));
        }
        r0 = fmaxf(r0, __shfl_xor_sync(0xffffffffu, r0, 1));
        r0 = fmaxf(r0, __shfl_xor_sync(0xffffffffu, r0, 2));
        r1 = fmaxf(r1, __shfl_xor_sync(0xffffffffu, r1, 1));
        r1 = fmaxf(r1, __shfl_xor_sync(0xffffffffu, r1, 2));

        float mn0 = fmaxf(m0, r0), mn1 = fmaxf(m1, r1);
        float al0 = (m0 == -INFINITY) ? 0.0f : __expf(m0 - mn0);
        float al1 = (m1 == -INFINITY) ? 0.0f : __expf(m1 - mn1);

        float ps0 = 0.0f, ps1 = 0.0f;
#pragma unroll
        for (int nt = 0; nt < 8; nt++) {
            float p0 = __expf(s[nt][0] - mn0);
            float p1 = __expf(s[nt][1] - mn0);
            float p2 = __expf(s[nt][2] - mn1);
            float p3 = __expf(s[nt][3] - mn1);
            s[nt][0] = p0; s[nt][1] = p1; s[nt][2] = p2; s[nt][3] = p3;
            ps0 += p0 + p1;
            ps1 += p2 + p3;
        }
        ps0 += __shfl_xor_sync(0xffffffffu, ps0, 1);
        ps0 += __shfl_xor_sync(0xffffffffu, ps0, 2);
        ps1 += __shfl_xor_sync(0xffffffffu, ps1, 1);
        ps1 += __shfl_xor_sync(0xffffffffu, ps1, 2);

        l0 = l0 * al0 + ps0;
        l1 = l1 * al1 + ps1;
        m0 = mn0;
        m1 = mn1;

#pragma unroll
        for (int nt = 0; nt < 8; nt++) {
            o[nt][0] *= al0; o[nt][1] *= al0;
            o[nt][2] *= al1; o[nt][3] *= al1;
        }

        // Stage P (tf32) into this warp's private rows of Ps
#pragma unroll
        for (int nt = 0; nt < 8; nt++) {
            Ps[(w16 + g) * AP + nt * 8 + 2 * tg]         = f2tf32(s[nt][0]);
            Ps[(w16 + g) * AP + nt * 8 + 2 * tg + 1]     = f2tf32(s[nt][1]);
            Ps[(w16 + g + 8) * AP + nt * 8 + 2 * tg]     = f2tf32(s[nt][2]);
            Ps[(w16 + g + 8) * AP + nt * 8 + 2 * tg + 1] = f2tf32(s[nt][3]);
        }
        __syncwarp();

#pragma unroll
        for (int ks = 0; ks < 8; ks++) {
            uint32_t ap[4];
            ap[0] = Ps[(w16 + g) * AP + ks * 8 + tg];
            ap[1] = Ps[(w16 + g + 8) * AP + ks * 8 + tg];
            ap[2] = Ps[(w16 + g) * AP + ks * 8 + tg + 4];
            ap[3] = Ps[(w16 + g + 8) * AP + ks * 8 + tg + 4];
#pragma unroll
            for (int nt = 0; nt < 8; nt++) {
                uint32_t b0 = Vc[(nt * 8 + g) * AP + ks * 8 + tg];
                uint32_t b1 = Vc[(nt * 8 + g) * AP + ks * 8 + tg + 4];
                mma_tf32(o[nt], ap, b0, b1);
            }
        }
        __syncwarp();
    }

    // Normalize, round to tf32-exact (gemm_o consumes raw), write ctx.
    const float inv0 = 1.0f / l0;
    const float inv1 = 1.0f / l1;
#pragma unroll
    for (int nt = 0; nt < 8; nt++) {
        int col = nt * 8 + 2 * tg;
        uint2 r0v = make_uint2(f2tf32(o[nt][0] * inv0), f2tf32(o[nt][1] * inv0));
        uint2 r1v = make_uint2(f2tf32(o[nt][2] * inv1), f2tf32(o[nt][3] * inv1));
        *(uint2*)(g_ctx + base_bh + (size_t)(q0 + w16 + g) * DD + col) = r0v;
        *(uint2*)(g_ctx + base_bh + (size_t)(q0 + w16 + g + 8) * DD + col) = r1v;
    }
}

// ---------------------------------------------------------------------------
extern "C" void kernel_launch(void* const* d_in, const int* in_sizes, int n_in,
                              void* d_out, int out_size) {
    const float* x  = (const float*)d_in[0];
    const float* wq = (const float*)d_in[1];
    const float* wk = (const float*)d_in[2];
    const float* wv = (const float*)d_in[3];
    const float* wo = (const float*)d_in[4];
    float* out = (float*)d_out;

    float *xr, *wqr, *wkr, *wvr, *wor, *v;
    cudaGetSymbolAddress((void**)&xr,  g_x);
    cudaGetSymbolAddress((void**)&wqr, g_wq);
    cudaGetSymbolAddress((void**)&wkr, g_wk);
    cudaGetSymbolAddress((void**)&wvr, g_wv);
    cudaGetSymbolAddress((void**)&wor, g_wo);
    cudaGetSymbolAddress((void**)&v,   g_v);

    cudaFuncSetAttribute(attn_tc, cudaFuncAttributeMaxDynamicSharedMemorySize,
                         ATTN_SMEM);
    cudaFuncSetAttribute(gemm_qkv, cudaFuncAttributeMaxDynamicSharedMemorySize,
                         GEMM_SMEM);
    cudaFuncSetAttribute(gemm_o, cudaFuncAttributeMaxDynamicSharedMemorySize,
                         GEMM_SMEM);

    // Pre-round GEMM operands to tf32-exact fp32.
    tf32_round<<<(M_TOT * DD) / 1024, 256>>>(x, xr);
    tf32_round<<<(DD * DD) / 1024, 256>>>(wq, wqr);
    tf32_round<<<(DD * DD) / 1024, 256>>>(wk, wkr);
    tf32_round<<<(DD * DD) / 1024, 256>>>(wv, wvr);
    tf32_round<<<(DD * DD) / 1024, 256>>>(wo, wor);

    // Fused Q/K/V projections: 24 n-tiles x 64 m-tiles
    gemm_qkv<<<dim3(24, M_TOT / 128), 256, GEMM_SMEM>>>();

    // RoPE (writes tf32-exact q/k); round v in place for raw attention staging.
    rope_kernel<<<(BB * SS * HH * (DK / 2)) / 256, 256>>>();
    tf32_round<<<(M_TOT * DD) / 1024, 256>>>(v, v);

    attn_tc<<<dim3(SS / 128, HH, BB), 256, ATTN_SMEM>>>();

    gemm_o<<<dim3(DD / 128, M_TOT / 128), 256, GEMM_SMEM>>>(out);
}